// round 13
// baseline (speedup 1.0000x reference)
#include <cuda_runtime.h>
#include <cuda_fp16.h>
#include <math.h>
#include <stdint.h>

// Problem constants
#define B_   2
#define S_   2048
#define D_   1024
#define H_   16
#define DH_  64
#define M_   (B_*S_)

// ---------------- scratch (device globals; no allocation) ----------------
__device__ __half g_inh[3*M_*D_];       // input activations hi (q,k,v order)
__device__ __half g_inl[3*M_*D_];       // input activations lo
__device__ __half g_wh[4*D_*D_];        // Wq,Wk,Wv,Wo fp16
__device__ __half g_qh[B_*H_*S_*DH_];   // Q hi (pre-scaled by 0.125)
__device__ __half g_ql[B_*H_*S_*DH_];   // Q lo (pre-scaled)
__device__ __half g_kh[B_*H_*S_*DH_];   // K fp16
__device__ __half g_vh[B_*H_*S_*DH_];   // V fp16
__device__ __half g_atth[M_*D_];        // attention out hi [B,S,D]
__device__ __half g_attl[M_*D_];        // attention out lo

__device__ __forceinline__ void cvt_hilo(float x, __half& h, __half& l) {
    h = __float2half_rn(x);
    l = __float2half_rn(x - __half2float(h));
}
__device__ __forceinline__ uint32_t h2_to_u32(__half2 h) {
    union { __half2 h2; uint32_t u; } cv;
    cv.h2 = h;
    return cv.u;
}
__device__ __forceinline__ void mma16816(float* d, const uint32_t* a, const uint32_t* b) {
    asm volatile(
        "mma.sync.aligned.m16n8k16.row.col.f32.f16.f16.f32 "
        "{%0,%1,%2,%3}, {%4,%5,%6,%7}, {%8,%9}, {%0,%1,%2,%3};\n"
        : "+f"(d[0]), "+f"(d[1]), "+f"(d[2]), "+f"(d[3])
        : "r"(a[0]), "r"(a[1]), "r"(a[2]), "r"(a[3]), "r"(b[0]), "r"(b[1]));
}
__device__ __forceinline__ void ldsm_x4(uint32_t* r, uint32_t a) {
    asm volatile("ldmatrix.sync.aligned.m8n8.x4.shared.b16 {%0,%1,%2,%3}, [%4];"
        : "=r"(r[0]), "=r"(r[1]), "=r"(r[2]), "=r"(r[3]) : "r"(a));
}
__device__ __forceinline__ void ldsm_x4_t(uint32_t* r, uint32_t a) {
    asm volatile("ldmatrix.sync.aligned.m8n8.x4.trans.shared.b16 {%0,%1,%2,%3}, [%4];"
        : "=r"(r[0]), "=r"(r[1]), "=r"(r[2]), "=r"(r[3]) : "r"(a));
}

// =====================================================================
// Elementwise converters (run once, up front)
// =====================================================================
__global__ void cvt_split(const float* __restrict__ in,
                          __half* __restrict__ hi, __half* __restrict__ lo, int n4)
{
    int i = blockIdx.x * blockDim.x + threadIdx.x;
    if (i >= n4) return;
    float4 v = ((const float4*)in)[i];
    __half h0,l0,h1,l1,h2,l2,h3,l3;
    cvt_hilo(v.x, h0, l0); cvt_hilo(v.y, h1, l1);
    cvt_hilo(v.z, h2, l2); cvt_hilo(v.w, h3, l3);
    ((uint2*)hi)[i] = make_uint2(h2_to_u32(__halves2half2(h0, h1)),
                                 h2_to_u32(__halves2half2(h2, h3)));
    ((uint2*)lo)[i] = make_uint2(h2_to_u32(__halves2half2(l0, l1)),
                                 h2_to_u32(__halves2half2(l2, l3)));
}
__global__ void cvt_w(const float* __restrict__ in, __half* __restrict__ out, int n4)
{
    int i = blockIdx.x * blockDim.x + threadIdx.x;
    if (i >= n4) return;
    float4 v = ((const float4*)in)[i];
    ((uint2*)out)[i] = make_uint2(h2_to_u32(__floats2half2_rn(v.x, v.y)),
                                  h2_to_u32(__floats2half2_rn(v.z, v.w)));
}

// =====================================================================
// fp16-input GEMM on raw mma.sync + ldmatrix.
// C[m][n] = sum_k (Ah+Al)[m][k]*Wh[n][k] + bias[n]  (2-pass A split)
// CTA 128x128, BK=32, 256 threads / 8 warps (2m x 4n), warp 64x32.
// Direct register epilogue (no smem staging).
// MODE 0: fp32 out [M][N]; MODE 1: Q hi/lo scaled 0.125 -> [B,H,S,DH];
// MODE 2: single fp16 -> [B,H,S,DH].
// =====================================================================
#define GLDT 40    // smem leading dim (halves); 80B rows, ldmatrix conflict-free

template<int MODE>
__global__ void __launch_bounds__(256) gemm_h(
    const __half* __restrict__ Ah, const __half* __restrict__ Al,
    const __half* __restrict__ Wh, const float* __restrict__ bias,
    float* __restrict__ outf, __half* __restrict__ oh, __half* __restrict__ ol)
{
    __shared__ __half sAh[128*GLDT];
    __shared__ __half sAl[128*GLDT];
    __shared__ __half sW [128*GLDT];

    const int tid = threadIdx.x;
    const int wid = tid >> 5, lane = tid & 31;
    const int warp_m = wid & 1, warp_n = wid >> 1;
    const int m0 = blockIdx.y * 128, n0 = blockIdx.x * 128;

    // load mapping: idx = u*256 + tid -> row = idx>>2 (+64/u), ch = idx&3
    const int lrow = tid >> 2;
    const int lch  = tid & 3;

    const int li = lane >> 3, l7 = lane & 7;
    const uint32_t bAh = (uint32_t)__cvta_generic_to_shared(sAh);
    const uint32_t bAl = (uint32_t)__cvta_generic_to_shared(sAl);
    const uint32_t bW  = (uint32_t)__cvta_generic_to_shared(sW);
    // A-frag (row-major m16k16): matrix i: row = (i&1)*8+l7, col=(i>>1)*8
    const uint32_t offA = ((uint32_t)((warp_m*64 + ((li & 1) << 3) + l7) * GLDT
                                       + ((li >> 1) << 3)) << 1);
    // W/B-frag (n8k16 pairs): matrix i: n = (i>>1)*8+l7, k = (i&1)*8
    const uint32_t offW = ((uint32_t)((warp_n*32 + ((li >> 1) << 3) + l7) * GLDT
                                       + ((li & 1) << 3)) << 1);

    float acc[4][4][4];
    #pragma unroll
    for (int mt = 0; mt < 4; mt++)
        #pragma unroll
        for (int nt = 0; nt < 4; nt++)
            #pragma unroll
            for (int t = 0; t < 4; t++) acc[mt][nt][t] = 0.f;

    for (int kt = 0; kt < 32; kt++) {
        const int k0 = kt * 32;
        uint4 pa[2], pl[2], pw[2];
        #pragma unroll
        for (int u = 0; u < 2; u++) {
            int row = lrow + u*64;
            pa[u] = *(const uint4*)&Ah[(size_t)(m0 + row)*1024 + k0 + lch*8];
            pl[u] = *(const uint4*)&Al[(size_t)(m0 + row)*1024 + k0 + lch*8];
            pw[u] = *(const uint4*)&Wh[(size_t)(n0 + row)*1024 + k0 + lch*8];
        }
        __syncthreads();   // (a) previous k-step's ldmatrix done
        #pragma unroll
        for (int u = 0; u < 2; u++) {
            int row = lrow + u*64;
            *(uint4*)&sAh[row*GLDT + lch*8] = pa[u];
            *(uint4*)&sAl[row*GLDT + lch*8] = pl[u];
            *(uint4*)&sW [row*GLDT + lch*8] = pw[u];
        }
        __syncthreads();   // (b) tile ready

        #pragma unroll
        for (int kk = 0; kk < 32; kk += 16) {
            uint32_t ah[4][4], al[4][4];
            #pragma unroll
            for (int mt = 0; mt < 4; mt++) {
                ldsm_x4(ah[mt], bAh + offA + ((mt*16*GLDT + kk) << 1));
                ldsm_x4(al[mt], bAl + offA + ((mt*16*GLDT + kk) << 1));
            }
            #pragma unroll
            for (int np = 0; np < 2; np++) {
                uint32_t wf[4];
                ldsm_x4(wf, bW + offW + ((np*16*GLDT + kk) << 1));
                #pragma unroll
                for (int mt = 0; mt < 4; mt++) {
                    mma16816(acc[mt][2*np],   ah[mt], wf);
                    mma16816(acc[mt][2*np],   al[mt], wf);
                    mma16816(acc[mt][2*np+1], ah[mt], wf + 2);
                    mma16816(acc[mt][2*np+1], al[mt], wf + 2);
                }
            }
        }
    }

    // ---- direct register epilogue ----
    const int g = lane >> 2, c = lane & 3;
    const int nw0 = n0 + warp_n*32;
    float2 bv[4];
    #pragma unroll
    for (int nt = 0; nt < 4; nt++) {
        int col = nw0 + nt*8 + 2*c;
        bv[nt] = make_float2(bias[col], bias[col+1]);
    }
    const int hh = nw0 >> 6, d0 = nw0 & 63;

    #pragma unroll
    for (int mt = 0; mt < 4; mt++) {
        int gm0 = m0 + warp_m*64 + mt*16 + g;
        int gm1 = gm0 + 8;
        #pragma unroll
        for (int nt = 0; nt < 4; nt++) {
            float v0 = acc[mt][nt][0] + bv[nt].x;
            float v1 = acc[mt][nt][1] + bv[nt].y;
            float v2 = acc[mt][nt][2] + bv[nt].x;
            float v3 = acc[mt][nt][3] + bv[nt].y;
            int col = nw0 + nt*8 + 2*c;
            if (MODE == 0) {
                *(float2*)&outf[(size_t)gm0*1024 + col] = make_float2(v0, v1);
                *(float2*)&outf[(size_t)gm1*1024 + col] = make_float2(v2, v3);
            } else {
                int d = d0 + nt*8 + 2*c;
                int b0 = gm0 >> 11, s0 = gm0 & 2047;
                int b1 = gm1 >> 11, s1 = gm1 & 2047;
                size_t a0 = (((size_t)(b0*H_ + hh))*S_ + s0)*DH_ + d;
                size_t a1 = (((size_t)(b1*H_ + hh))*S_ + s1)*DH_ + d;
                if (MODE == 1) {
                    v0 *= 0.125f; v1 *= 0.125f; v2 *= 0.125f; v3 *= 0.125f;
                    __half h0,l0,h1,l1,h2,l2,h3,l3;
                    cvt_hilo(v0, h0, l0); cvt_hilo(v1, h1, l1);
                    cvt_hilo(v2, h2, l2); cvt_hilo(v3, h3, l3);
                    *(uint32_t*)&oh[a0] = h2_to_u32(__halves2half2(h0, h1));
                    *(uint32_t*)&ol[a0] = h2_to_u32(__halves2half2(l0, l1));
                    *(uint32_t*)&oh[a1] = h2_to_u32(__halves2half2(h2, h3));
                    *(uint32_t*)&ol[a1] = h2_to_u32(__halves2half2(l2, l3));
                } else {
                    *(uint32_t*)&oh[a0] = h2_to_u32(__floats2half2_rn(v0, v1));
                    *(uint32_t*)&oh[a1] = h2_to_u32(__floats2half2_rn(v2, v3));
                }
            }
        }
    }
}

// =====================================================================
// Flash attention — unchanged mainloop from R12 (214.6us validated);
// epilogue now writes hi/lo fp16 for the O-projection.
// =====================================================================
#define TLD 72

#define AT_QHI 0
#define AT_QLO (AT_QHI + 128*TLD*2)
#define AT_K   (AT_QLO + 128*TLD*2)
#define AT_V   (AT_K   + 128*TLD*2)
#define ATT_SMEM (AT_V + 128*TLD*2)      // 73728

__global__ void __launch_bounds__(256, 1) attn_mma()
{
    extern __shared__ char smem[];
    __half* Qhi = (__half*)(smem + AT_QHI);
    __half* Qlo = (__half*)(smem + AT_QLO);
    __half* Ks  = (__half*)(smem + AT_K);
    __half* Vs  = (__half*)(smem + AT_V);

    const int tid = threadIdx.x;
    const int wid = tid >> 5;
    const int lane = tid & 31;
    const int m0 = wid * 16;
    const int bh = blockIdx.y;
    const int q0 = blockIdx.x * 128;

    const __half* qh_base = g_qh + (size_t)bh*S_*DH_;
    const __half* ql_base = g_ql + (size_t)bh*S_*DH_;
    const __half* k_base  = g_kh + (size_t)bh*S_*DH_;
    const __half* v_base  = g_vh + (size_t)bh*S_*DH_;

    const int lrow = tid >> 3;
    const int lcu  = tid & 7;

    const uint32_t sb = (uint32_t)__cvta_generic_to_shared(smem);
    const int li = lane >> 3;
    const int l7 = lane & 7;
    const uint32_t aQ_off = ((uint32_t)((m0 + ((li & 1) << 3) + l7) * TLD
                                         + ((li >> 1) << 3)) << 1);
    const uint32_t aQhi = sb + AT_QHI + aQ_off;
    const uint32_t aQlo = sb + AT_QLO + aQ_off;
    const uint32_t aK = sb + AT_K +
        ((uint32_t)((((li >> 1) << 3) + l7) * TLD + ((li & 1) << 3)) << 1);
    const uint32_t aV = sb + AT_V +
        ((uint32_t)((((li & 1) << 3) + l7) * TLD + ((li >> 1) << 3)) << 1);

    #pragma unroll
    for (int u = 0; u < 4; u++) {
        int row = lrow + u*32;
        uint4 vh = *(const uint4*)&qh_base[(size_t)(q0 + row)*DH_ + lcu*8];
        uint4 vl = *(const uint4*)&ql_base[(size_t)(q0 + row)*DH_ + lcu*8];
        *(uint4*)&Qhi[row*TLD + lcu*8] = vh;
        *(uint4*)&Qlo[row*TLD + lcu*8] = vl;
    }

    float O[8][4];
    #pragma unroll
    for (int n = 0; n < 8; n++)
        #pragma unroll
        for (int t = 0; t < 4; t++) O[n][t] = 0.f;
    float mr0 = -INFINITY, mr1 = -INFINITY;
    float lr0 = 0.f, lr1 = 0.f;

    for (int kt = 0; kt < S_/128; kt++) {
        const int k0g = kt * 128;
        uint4 rk[4], rv[4];
        #pragma unroll
        for (int u = 0; u < 4; u++) {
            int row = lrow + u*32;
            rk[u] = *(const uint4*)&k_base[(size_t)(k0g + row)*DH_ + lcu*8];
            rv[u] = *(const uint4*)&v_base[(size_t)(k0g + row)*DH_ + lcu*8];
        }
        __syncthreads();
        #pragma unroll
        for (int u = 0; u < 4; u++) {
            int row = lrow + u*32;
            *(uint4*)&Ks[row*TLD + lcu*8] = rk[u];
            *(uint4*)&Vs[row*TLD + lcu*8] = rv[u];
        }
        __syncthreads();

        float sacc[16][4];
        #pragma unroll
        for (int n = 0; n < 16; n++)
            #pragma unroll
            for (int t = 0; t < 4; t++) sacc[n][t] = 0.f;

        #pragma unroll
        for (int kk = 0; kk < 64; kk += 16) {
            uint32_t qh[4], ql[4];
            ldsm_x4(qh, aQhi + (kk << 1));
            ldsm_x4(ql, aQlo + (kk << 1));
            #pragma unroll
            for (int np = 0; np < 8; np++) {
                uint32_t kf[4];
                ldsm_x4(kf, aK + ((np*16*TLD + kk) << 1));
                mma16816(sacc[2*np],   qh, kf);
                mma16816(sacc[2*np],   ql, kf);
                mma16816(sacc[2*np+1], qh, kf + 2);
                mma16816(sacc[2*np+1], ql, kf + 2);
            }
        }

        float mx0 = -INFINITY, mx1 = -INFINITY;
        #pragma unroll
        for (int n = 0; n < 16; n++) {
            mx0 = fmaxf(mx0, fmaxf(sacc[n][0], sacc[n][1]));
            mx1 = fmaxf(mx1, fmaxf(sacc[n][2], sacc[n][3]));
        }
        mx0 = fmaxf(mx0, __shfl_xor_sync(0xffffffffu, mx0, 1));
        mx0 = fmaxf(mx0, __shfl_xor_sync(0xffffffffu, mx0, 2));
        mx1 = fmaxf(mx1, __shfl_xor_sync(0xffffffffu, mx1, 1));
        mx1 = fmaxf(mx1, __shfl_xor_sync(0xffffffffu, mx1, 2));
        float m0n = fmaxf(mr0, mx0), m1n = fmaxf(mr1, mx1);
        float al0 = __expf(mr0 - m0n), al1 = __expf(mr1 - m1n);
        mr0 = m0n; mr1 = m1n;

        uint32_t pa[8][4];
        float sum0 = 0.f, sum1 = 0.f;
        #pragma unroll
        for (int j = 0; j < 8; j++) {
            float p00 = __expf(sacc[2*j][0] - m0n);
            float p01 = __expf(sacc[2*j][1] - m0n);
            float p10 = __expf(sacc[2*j][2] - m1n);
            float p11 = __expf(sacc[2*j][3] - m1n);
            float p04 = __expf(sacc[2*j+1][0] - m0n);
            float p05 = __expf(sacc[2*j+1][1] - m0n);
            float p14 = __expf(sacc[2*j+1][2] - m1n);
            float p15 = __expf(sacc[2*j+1][3] - m1n);
            sum0 += p00 + p01 + p04 + p05;
            sum1 += p10 + p11 + p14 + p15;
            pa[j][0] = h2_to_u32(__floats2half2_rn(p00, p01));
            pa[j][1] = h2_to_u32(__floats2half2_rn(p10, p11));
            pa[j][2] = h2_to_u32(__floats2half2_rn(p04, p05));
            pa[j][3] = h2_to_u32(__floats2half2_rn(p14, p15));
        }
        sum0 += __shfl_xor_sync(0xffffffffu, sum0, 1);
        sum0 += __shfl_xor_sync(0xffffffffu, sum0, 2);
        sum1 += __shfl_xor_sync(0xffffffffu, sum1, 1);
        sum1 += __shfl_xor_sync(0xffffffffu, sum1, 2);
        lr0 = lr0*al0 + sum0;
        lr1 = lr1*al1 + sum1;

        #pragma unroll
        for (int n = 0; n < 8; n++) {
            O[n][0] *= al0; O[n][1] *= al0;
            O[n][2] *= al1; O[n][3] *= al1;
        }
        #pragma unroll
        for (int j = 0; j < 8; j++) {
            #pragma unroll
            for (int nvp = 0; nvp < 4; nvp++) {
                uint32_t vf[4];
                ldsm_x4_t(vf, aV + ((j*16*TLD + nvp*16) << 1));
                mma16816(O[2*nvp],   pa[j], vf);
                mma16816(O[2*nvp+1], pa[j], vf + 2);
            }
        }
    }

    // ---- normalize + write hi/lo fp16 [B,S,D] ----
    const int g = lane >> 2;
    const int c = lane & 3;
    const int b = bh >> 4, h = bh & 15;
    float il0 = 1.0f / lr0, il1 = 1.0f / lr1;
    const int r0 = q0 + m0 + g, r1 = r0 + 8;
    #pragma unroll
    for (int nv = 0; nv < 8; nv++) {
        int col = h*DH_ + nv*8 + 2*c;
        size_t a0 = ((size_t)(b*S_ + r0))*D_ + col;
        size_t a1 = ((size_t)(b*S_ + r1))*D_ + col;
        __half h0,l0,h1,l1,h2,l2,h3,l3;
        cvt_hilo(O[nv][0]*il0, h0, l0); cvt_hilo(O[nv][1]*il0, h1, l1);
        cvt_hilo(O[nv][2]*il1, h2, l2); cvt_hilo(O[nv][3]*il1, h3, l3);
        *(uint32_t*)&g_atth[a0] = h2_to_u32(__halves2half2(h0, h1));
        *(uint32_t*)&g_attl[a0] = h2_to_u32(__halves2half2(l0, l1));
        *(uint32_t*)&g_atth[a1] = h2_to_u32(__halves2half2(h2, h3));
        *(uint32_t*)&g_attl[a1] = h2_to_u32(__halves2half2(l2, l3));
    }
}

// =====================================================================
// Launch
// =====================================================================
extern "C" void kernel_launch(void* const* d_in, const int* in_sizes, int n_in,
                              void* d_out, int out_size)
{
    const float* query  = (const float*)d_in[0];
    const float* keys   = (const float*)d_in[1];
    const float* values = (const float*)d_in[2];
    const float* Wq = (const float*)d_in[3];
    const float* bq = (const float*)d_in[4];
    const float* Wk = (const float*)d_in[5];
    const float* bk = (const float*)d_in[6];
    const float* Wv = (const float*)d_in[7];
    const float* bv = (const float*)d_in[8];
    const float* Wo = (const float*)d_in[9];
    const float* bo = (const float*)d_in[10];
    float* out = (float*)d_out;

    __half *inh, *inl, *wh, *qhp, *qlp, *khp, *vhp, *athp, *atlp;
    cudaGetSymbolAddress((void**)&inh,  g_inh);
    cudaGetSymbolAddress((void**)&inl,  g_inl);
    cudaGetSymbolAddress((void**)&wh,   g_wh);
    cudaGetSymbolAddress((void**)&qhp,  g_qh);
    cudaGetSymbolAddress((void**)&qlp,  g_ql);
    cudaGetSymbolAddress((void**)&khp,  g_kh);
    cudaGetSymbolAddress((void**)&vhp,  g_vh);
    cudaGetSymbolAddress((void**)&athp, g_atth);
    cudaGetSymbolAddress((void**)&atlp, g_attl);

    cudaFuncSetAttribute(attn_mma,
                         cudaFuncAttributeMaxDynamicSharedMemorySize, ATT_SMEM);

    const int N4I = M_*D_/4;    // 1,048,576
    const int N4W = D_*D_/4;    // 262,144
    cvt_split<<<(N4I+255)/256, 256>>>(query,  inh,            inl,            N4I);
    cvt_split<<<(N4I+255)/256, 256>>>(keys,   inh + M_*D_,    inl + M_*D_,    N4I);
    cvt_split<<<(N4I+255)/256, 256>>>(values, inh + 2*M_*D_,  inl + 2*M_*D_,  N4I);
    cvt_w<<<(N4W+255)/256, 256>>>(Wq, wh,            N4W);
    cvt_w<<<(N4W+255)/256, 256>>>(Wk, wh + D_*D_,    N4W);
    cvt_w<<<(N4W+255)/256, 256>>>(Wv, wh + 2*D_*D_,  N4W);
    cvt_w<<<(N4W+255)/256, 256>>>(Wo, wh + 3*D_*D_,  N4W);

    dim3 gemm_grid(D_/128, M_/128);   // (8, 32)
    gemm_h<1><<<gemm_grid, 256>>>(inh,           inl,           wh,          bq,
                                  nullptr, qhp, qlp);
    gemm_h<2><<<gemm_grid, 256>>>(inh + M_*D_,   inl + M_*D_,   wh + D_*D_,  bk,
                                  nullptr, khp, nullptr);
    gemm_h<2><<<gemm_grid, 256>>>(inh + 2*M_*D_, inl + 2*M_*D_, wh + 2*D_*D_, bv,
                                  nullptr, vhp, nullptr);

    attn_mma<<<dim3(S_/128, B_*H_), 256, ATT_SMEM>>>();

    gemm_h<0><<<gemm_grid, 256>>>(athp, atlp, wh + 3*D_*D_, bo,
                                  out, nullptr, nullptr);
}

// round 14
// speedup vs baseline: 1.0678x; 1.0678x over previous
#include <cuda_runtime.h>
#include <cuda_fp16.h>
#include <mma.h>
#include <math.h>
#include <stdint.h>

using namespace nvcuda;

// Problem constants
#define B_   2
#define S_   2048
#define D_   1024
#define H_   16
#define DH_  64
#define M_   (B_*S_)

// ---------------- scratch (device globals; no allocation) ----------------
__device__ __half g_qh[B_*H_*S_*DH_];   // Q hi (pre-scaled by 0.125)
__device__ __half g_ql[B_*H_*S_*DH_];   // Q lo (pre-scaled)
__device__ __half g_kh[B_*H_*S_*DH_];   // K fp16
__device__ __half g_vh[B_*H_*S_*DH_];   // V fp16
__device__ float  g_att[B_*S_*D_];      // attention out [B,S,D] fp32

__device__ __forceinline__ void cvt_hilo(float x, __half& h, __half& l) {
    h = __float2half_rn(x);
    l = __float2half_rn(x - __half2float(h));
}

__device__ __forceinline__ uint32_t h2_to_u32(__half2 h) {
    union { __half2 h2; uint32_t u; } cv;
    cv.h2 = h;
    return cv.u;
}

// m16n8k16 fp16 MMA, fp32 accumulate (HMMA.16816)
__device__ __forceinline__ void mma16816(float* d, const uint32_t* a, const uint32_t* b) {
    asm volatile(
        "mma.sync.aligned.m16n8k16.row.col.f32.f16.f16.f32 "
        "{%0,%1,%2,%3}, {%4,%5,%6,%7}, {%8,%9}, {%0,%1,%2,%3};\n"
        : "+f"(d[0]), "+f"(d[1]), "+f"(d[2]), "+f"(d[3])
        : "r"(a[0]), "r"(a[1]), "r"(a[2]), "r"(a[3]), "r"(b[0]), "r"(b[1]));
}

__device__ __forceinline__ void ldsm_x4(uint32_t* r, uint32_t a) {
    asm volatile("ldmatrix.sync.aligned.m8n8.x4.shared.b16 {%0,%1,%2,%3}, [%4];"
        : "=r"(r[0]), "=r"(r[1]), "=r"(r[2]), "=r"(r[3]) : "r"(a));
}
__device__ __forceinline__ void ldsm_x4_t(uint32_t* r, uint32_t a) {
    asm volatile("ldmatrix.sync.aligned.m8n8.x4.trans.shared.b16 {%0,%1,%2,%3}, [%4];"
        : "=r"(r[0]), "=r"(r[1]), "=r"(r[2]), "=r"(r[3]) : "r"(a));
}

// =====================================================================
// wmma fp16 split GEMM — 2-pass: A exact (hi+lo), W single fp16.
// R14 change vs R12: gmem loads for tile kt+1 issue AFTER the smem store
// barrier of tile kt and BEFORE tile kt's MMA — LDG latency hidden under
// the MMA phase instead of exposed on the critical path.
// MODE 0: fp32 out [M][N] (final projection)
// MODE 1: Q -> hi/lo half pair [B,H,S,DH], scaled by 0.125
// MODE 2: K/V -> single half [B,H,S,DH]
// =====================================================================
#define BKW 32
#define LDT 40
#define EPLD 36
#define GW_SMEM 73728

template<int MODE>
__global__ void __launch_bounds__(256) gemm_wmma(
    const float* __restrict__ A, const float* __restrict__ W,
    const float* __restrict__ bias, float* __restrict__ outf,
    __half* __restrict__ outh_hi, __half* __restrict__ outh_lo)
{
    extern __shared__ char smem[];
    __half* sA_hi = (__half*)smem;
    __half* sA_lo = sA_hi + 128*LDT;
    __half* sW_hi = sA_lo + 128*LDT;
    float*  sEp   = (float*)smem;

    const int tid = threadIdx.x;
    const int wid = tid >> 5, lid = tid & 31;
    const int warp_m = wid & 1;
    const int warp_n = wid >> 1;
    const int m0 = blockIdx.y * 128, n0 = blockIdx.x * 128;

    const int lrow = tid >> 3;
    const int lc4  = tid & 7;

    wmma::fragment<wmma::accumulator, 16, 16, 16, float> acc[4][2];
    #pragma unroll
    for (int m = 0; m < 4; m++)
        #pragma unroll
        for (int n = 0; n < 2; n++) wmma::fill_fragment(acc[m][n], 0.0f);

    // preload tile 0
    float4 ra[4], rw[4];
    #pragma unroll
    for (int u = 0; u < 4; u++) {
        int row = lrow + u*32;
        ra[u] = *(const float4*)&A[(size_t)(m0 + row)*1024 + lc4*4];
        rw[u] = *(const float4*)&W[(size_t)(n0 + row)*1024 + lc4*4];
    }

    for (int kt = 0; kt < 1024/BKW; kt++) {
        __syncthreads();   // (a) previous k-step's fragment loads done

        #pragma unroll
        for (int u = 0; u < 4; u++) {
            int row = lrow + u*32;
            int off = row*LDT + lc4*4;
            __half h0,l0,h1,l1,h2,l2,h3,l3;
            cvt_hilo(ra[u].x, h0, l0); cvt_hilo(ra[u].y, h1, l1);
            cvt_hilo(ra[u].z, h2, l2); cvt_hilo(ra[u].w, h3, l3);
            ((__half2*)&sA_hi[off])[0] = __halves2half2(h0, h1);
            ((__half2*)&sA_hi[off])[1] = __halves2half2(h2, h3);
            ((__half2*)&sA_lo[off])[0] = __halves2half2(l0, l1);
            ((__half2*)&sA_lo[off])[1] = __halves2half2(l2, l3);
            h0 = __float2half_rn(rw[u].x); h1 = __float2half_rn(rw[u].y);
            h2 = __float2half_rn(rw[u].z); h3 = __float2half_rn(rw[u].w);
            ((__half2*)&sW_hi[off])[0] = __halves2half2(h0, h1);
            ((__half2*)&sW_hi[off])[1] = __halves2half2(h2, h3);
        }
        __syncthreads();   // (b) tile ready

        // prefetch NEXT tile: LDG in flight under the MMA below
        if (kt + 1 < 1024/BKW) {
            const int k1 = (kt + 1) * BKW;
            #pragma unroll
            for (int u = 0; u < 4; u++) {
                int row = lrow + u*32;
                ra[u] = *(const float4*)&A[(size_t)(m0 + row)*1024 + k1 + lc4*4];
                rw[u] = *(const float4*)&W[(size_t)(n0 + row)*1024 + k1 + lc4*4];
            }
        }

        #pragma unroll
        for (int kk = 0; kk < BKW; kk += 16) {
            wmma::fragment<wmma::matrix_a, 16, 16, 16, __half, wmma::row_major> ahi[4], alo[4];
            #pragma unroll
            for (int m = 0; m < 4; m++) {
                int r = warp_m*64 + m*16;
                wmma::load_matrix_sync(ahi[m], &sA_hi[r*LDT + kk], LDT);
                wmma::load_matrix_sync(alo[m], &sA_lo[r*LDT + kk], LDT);
            }
            #pragma unroll
            for (int n = 0; n < 2; n++) {
                int c = warp_n*32 + n*16;
                wmma::fragment<wmma::matrix_b, 16, 16, 16, __half, wmma::col_major> bhi;
                wmma::load_matrix_sync(bhi, &sW_hi[c*LDT + kk], LDT);
                #pragma unroll
                for (int m = 0; m < 4; m++) {
                    wmma::mma_sync(acc[m][n], ahi[m], bhi, acc[m][n]);
                    wmma::mma_sync(acc[m][n], alo[m], bhi, acc[m][n]);
                }
            }
        }
    }

    __syncthreads();
    float* ep = sEp + wid * 64 * EPLD;
    #pragma unroll
    for (int m = 0; m < 4; m++)
        #pragma unroll
        for (int n = 0; n < 2; n++)
            wmma::store_matrix_sync(&ep[(m*16)*EPLD + n*16], acc[m][n],
                                    EPLD, wmma::mem_row_major);
    __syncwarp();

    const int nw0 = n0 + warp_n*32;
    #pragma unroll
    for (int rr = 0; rr < 2; rr++) {
        int r = lid + rr*32;
        int gm = m0 + warp_m*64 + r;
        if (MODE == 0) {
            #pragma unroll
            for (int c4 = 0; c4 < 8; c4++) {
                float4 v = *(float4*)&ep[r*EPLD + c4*4];
                int n = nw0 + c4*4;
                v.x += bias[n+0]; v.y += bias[n+1];
                v.z += bias[n+2]; v.w += bias[n+3];
                *(float4*)&outf[(size_t)gm*1024 + n] = v;
            }
        } else {
            int b = gm >> 11, s = gm & 2047;
            int h = nw0 >> 6, d0 = nw0 & 63;
            size_t base = (((size_t)(b*H_ + h))*S_ + s)*DH_ + d0;
            #pragma unroll
            for (int c4 = 0; c4 < 8; c4++) {
                float4 v = *(float4*)&ep[r*EPLD + c4*4];
                int n = nw0 + c4*4;
                v.x += bias[n+0]; v.y += bias[n+1];
                v.z += bias[n+2]; v.w += bias[n+3];
                if (MODE == 1) {
                    v.x *= 0.125f; v.y *= 0.125f; v.z *= 0.125f; v.w *= 0.125f;
                    __half h0,l0,h1,l1,h2,l2,h3,l3;
                    cvt_hilo(v.x, h0, l0); cvt_hilo(v.y, h1, l1);
                    cvt_hilo(v.z, h2, l2); cvt_hilo(v.w, h3, l3);
                    uint2 hi = make_uint2(h2_to_u32(__halves2half2(h0, h1)),
                                          h2_to_u32(__halves2half2(h2, h3)));
                    uint2 lo = make_uint2(h2_to_u32(__halves2half2(l0, l1)),
                                          h2_to_u32(__halves2half2(l2, l3)));
                    *(uint2*)&outh_hi[base + c4*4] = hi;
                    *(uint2*)&outh_lo[base + c4*4] = lo;
                } else {
                    uint2 hv = make_uint2(
                        h2_to_u32(__floats2half2_rn(v.x, v.y)),
                        h2_to_u32(__floats2half2_rn(v.z, v.w)));
                    *(uint2*)&outh_hi[base + c4*4] = hv;
                }
            }
        }
    }
}

// =====================================================================
// Flash attention — raw mma.sync + ldmatrix, fp16 scratch inputs.
// Unchanged from R12 (214.6us validated).
// =====================================================================
#define TLD 72          // leading dim (halves); 144B rows

#define AT_QHI 0
#define AT_QLO (AT_QHI + 128*TLD*2)      // 18432
#define AT_K   (AT_QLO + 128*TLD*2)      // 36864
#define AT_V   (AT_K   + 128*TLD*2)      // 55296
#define ATT_SMEM (AT_V + 128*TLD*2)      // 73728

__global__ void __launch_bounds__(256, 1) attn_mma()
{
    extern __shared__ char smem[];
    __half* Qhi = (__half*)(smem + AT_QHI);
    __half* Qlo = (__half*)(smem + AT_QLO);
    __half* Ks  = (__half*)(smem + AT_K);
    __half* Vs  = (__half*)(smem + AT_V);

    const int tid = threadIdx.x;
    const int wid = tid >> 5;
    const int lane = tid & 31;
    const int m0 = wid * 16;
    const int bh = blockIdx.y;
    const int q0 = blockIdx.x * 128;

    const __half* qh_base = g_qh + (size_t)bh*S_*DH_;
    const __half* ql_base = g_ql + (size_t)bh*S_*DH_;
    const __half* k_base  = g_kh + (size_t)bh*S_*DH_;
    const __half* v_base  = g_vh + (size_t)bh*S_*DH_;

    const int lrow = tid >> 3;
    const int lcu  = tid & 7;

    const uint32_t sb = (uint32_t)__cvta_generic_to_shared(smem);
    const int li = lane >> 3;
    const int l7 = lane & 7;
    const uint32_t aQ_off = ((uint32_t)((m0 + ((li & 1) << 3) + l7) * TLD
                                         + ((li >> 1) << 3)) << 1);
    const uint32_t aQhi = sb + AT_QHI + aQ_off;
    const uint32_t aQlo = sb + AT_QLO + aQ_off;
    const uint32_t aK = sb + AT_K +
        ((uint32_t)((((li >> 1) << 3) + l7) * TLD + ((li & 1) << 3)) << 1);
    const uint32_t aV = sb + AT_V +
        ((uint32_t)((((li & 1) << 3) + l7) * TLD + ((li >> 1) << 3)) << 1);

    #pragma unroll
    for (int u = 0; u < 4; u++) {
        int row = lrow + u*32;
        uint4 vh = *(const uint4*)&qh_base[(size_t)(q0 + row)*DH_ + lcu*8];
        uint4 vl = *(const uint4*)&ql_base[(size_t)(q0 + row)*DH_ + lcu*8];
        *(uint4*)&Qhi[row*TLD + lcu*8] = vh;
        *(uint4*)&Qlo[row*TLD + lcu*8] = vl;
    }

    float O[8][4];
    #pragma unroll
    for (int n = 0; n < 8; n++)
        #pragma unroll
        for (int t = 0; t < 4; t++) O[n][t] = 0.f;
    float mr0 = -INFINITY, mr1 = -INFINITY;
    float lr0 = 0.f, lr1 = 0.f;

    for (int kt = 0; kt < S_/128; kt++) {
        const int k0g = kt * 128;
        uint4 rk[4], rv[4];
        #pragma unroll
        for (int u = 0; u < 4; u++) {
            int row = lrow + u*32;
            rk[u] = *(const uint4*)&k_base[(size_t)(k0g + row)*DH_ + lcu*8];
            rv[u] = *(const uint4*)&v_base[(size_t)(k0g + row)*DH_ + lcu*8];
        }
        __syncthreads();
        #pragma unroll
        for (int u = 0; u < 4; u++) {
            int row = lrow + u*32;
            *(uint4*)&Ks[row*TLD + lcu*8] = rk[u];
            *(uint4*)&Vs[row*TLD + lcu*8] = rv[u];
        }
        __syncthreads();

        float sacc[16][4];
        #pragma unroll
        for (int n = 0; n < 16; n++)
            #pragma unroll
            for (int t = 0; t < 4; t++) sacc[n][t] = 0.f;

        #pragma unroll
        for (int kk = 0; kk < 64; kk += 16) {
            uint32_t qh[4], ql[4];
            ldsm_x4(qh, aQhi + (kk << 1));
            ldsm_x4(ql, aQlo + (kk << 1));
            #pragma unroll
            for (int np = 0; np < 8; np++) {
                uint32_t kf[4];
                ldsm_x4(kf, aK + ((np*16*TLD + kk) << 1));
                mma16816(sacc[2*np],   qh, kf);
                mma16816(sacc[2*np],   ql, kf);
                mma16816(sacc[2*np+1], qh, kf + 2);
                mma16816(sacc[2*np+1], ql, kf + 2);
            }
        }

        float mx0 = -INFINITY, mx1 = -INFINITY;
        #pragma unroll
        for (int n = 0; n < 16; n++) {
            mx0 = fmaxf(mx0, fmaxf(sacc[n][0], sacc[n][1]));
            mx1 = fmaxf(mx1, fmaxf(sacc[n][2], sacc[n][3]));
        }
        mx0 = fmaxf(mx0, __shfl_xor_sync(0xffffffffu, mx0, 1));
        mx0 = fmaxf(mx0, __shfl_xor_sync(0xffffffffu, mx0, 2));
        mx1 = fmaxf(mx1, __shfl_xor_sync(0xffffffffu, mx1, 1));
        mx1 = fmaxf(mx1, __shfl_xor_sync(0xffffffffu, mx1, 2));
        float m0n = fmaxf(mr0, mx0), m1n = fmaxf(mr1, mx1);
        float al0 = __expf(mr0 - m0n), al1 = __expf(mr1 - m1n);
        mr0 = m0n; mr1 = m1n;

        uint32_t pa[8][4];
        float sum0 = 0.f, sum1 = 0.f;
        #pragma unroll
        for (int j = 0; j < 8; j++) {
            float p00 = __expf(sacc[2*j][0] - m0n);
            float p01 = __expf(sacc[2*j][1] - m0n);
            float p10 = __expf(sacc[2*j][2] - m1n);
            float p11 = __expf(sacc[2*j][3] - m1n);
            float p04 = __expf(sacc[2*j+1][0] - m0n);
            float p05 = __expf(sacc[2*j+1][1] - m0n);
            float p14 = __expf(sacc[2*j+1][2] - m1n);
            float p15 = __expf(sacc[2*j+1][3] - m1n);
            sum0 += p00 + p01 + p04 + p05;
            sum1 += p10 + p11 + p14 + p15;
            pa[j][0] = h2_to_u32(__floats2half2_rn(p00, p01));
            pa[j][1] = h2_to_u32(__floats2half2_rn(p10, p11));
            pa[j][2] = h2_to_u32(__floats2half2_rn(p04, p05));
            pa[j][3] = h2_to_u32(__floats2half2_rn(p14, p15));
        }
        sum0 += __shfl_xor_sync(0xffffffffu, sum0, 1);
        sum0 += __shfl_xor_sync(0xffffffffu, sum0, 2);
        sum1 += __shfl_xor_sync(0xffffffffu, sum1, 1);
        sum1 += __shfl_xor_sync(0xffffffffu, sum1, 2);
        lr0 = lr0*al0 + sum0;
        lr1 = lr1*al1 + sum1;

        #pragma unroll
        for (int n = 0; n < 8; n++) {
            O[n][0] *= al0; O[n][1] *= al0;
            O[n][2] *= al1; O[n][3] *= al1;
        }
        #pragma unroll
        for (int j = 0; j < 8; j++) {
            #pragma unroll
            for (int nvp = 0; nvp < 4; nvp++) {
                uint32_t vf[4];
                ldsm_x4_t(vf, aV + ((j*16*TLD + nvp*16) << 1));
                mma16816(O[2*nvp],   pa[j], vf);
                mma16816(O[2*nvp+1], pa[j], vf + 2);
            }
        }
    }

    // ---- normalize + write [B,S,D] ----
    const int g = lane >> 2;
    const int c = lane & 3;
    const int b = bh >> 4, h = bh & 15;
    float il0 = 1.0f / lr0, il1 = 1.0f / lr1;
    const int r0 = q0 + m0 + g, r1 = r0 + 8;
    #pragma unroll
    for (int nv = 0; nv < 8; nv++) {
        int col = h*DH_ + nv*8 + 2*c;
        float2 v0 = make_float2(O[nv][0]*il0, O[nv][1]*il0);
        float2 v1 = make_float2(O[nv][2]*il1, O[nv][3]*il1);
        *(float2*)&g_att[((size_t)(b*S_ + r0))*D_ + col] = v0;
        *(float2*)&g_att[((size_t)(b*S_ + r1))*D_ + col] = v1;
    }
}

// =====================================================================
// Launch
// =====================================================================
extern "C" void kernel_launch(void* const* d_in, const int* in_sizes, int n_in,
                              void* d_out, int out_size)
{
    const float* query  = (const float*)d_in[0];
    const float* keys   = (const float*)d_in[1];
    const float* values = (const float*)d_in[2];
    const float* Wq = (const float*)d_in[3];
    const float* bq = (const float*)d_in[4];
    const float* Wk = (const float*)d_in[5];
    const float* bk = (const float*)d_in[6];
    const float* Wv = (const float*)d_in[7];
    const float* bv = (const float*)d_in[8];
    const float* Wo = (const float*)d_in[9];
    const float* bo = (const float*)d_in[10];
    float* out = (float*)d_out;

    __half *qhp, *qlp, *khp, *vhp;
    float *ap;
    cudaGetSymbolAddress((void**)&qhp, g_qh);
    cudaGetSymbolAddress((void**)&qlp, g_ql);
    cudaGetSymbolAddress((void**)&khp, g_kh);
    cudaGetSymbolAddress((void**)&vhp, g_vh);
    cudaGetSymbolAddress((void**)&ap,  g_att);

    cudaFuncSetAttribute(gemm_wmma<0>,
                         cudaFuncAttributeMaxDynamicSharedMemorySize, GW_SMEM);
    cudaFuncSetAttribute(gemm_wmma<1>,
                         cudaFuncAttributeMaxDynamicSharedMemorySize, GW_SMEM);
    cudaFuncSetAttribute(gemm_wmma<2>,
                         cudaFuncAttributeMaxDynamicSharedMemorySize, GW_SMEM);
    cudaFuncSetAttribute(attn_mma,
                         cudaFuncAttributeMaxDynamicSharedMemorySize, ATT_SMEM);

    dim3 gemm_grid(D_/128, M_/128);   // (8, 32)
    gemm_wmma<1><<<gemm_grid, 256, GW_SMEM>>>(query,  Wq, bq, nullptr, qhp, qlp);
    gemm_wmma<2><<<gemm_grid, 256, GW_SMEM>>>(keys,   Wk, bk, nullptr, khp, nullptr);
    gemm_wmma<2><<<gemm_grid, 256, GW_SMEM>>>(values, Wv, bv, nullptr, vhp, nullptr);

    attn_mma<<<dim3(S_/128, B_*H_), 256, ATT_SMEM>>>();

    gemm_wmma<0><<<gemm_grid, 256, GW_SMEM>>>(ap, Wo, bo, out, nullptr, nullptr);
}

// round 15
// speedup vs baseline: 1.2834x; 1.2019x over previous
#include <cuda_runtime.h>
#include <cuda_fp16.h>
#include <mma.h>
#include <math.h>
#include <stdint.h>

using namespace nvcuda;

// Problem constants
#define B_   2
#define S_   2048
#define D_   1024
#define H_   16
#define DH_  64
#define M_   (B_*S_)

// ---------------- scratch (device globals; no allocation) ----------------
__device__ __half g_qh[B_*H_*S_*DH_];   // Q fp16 (pre-scaled by 0.125)
__device__ __half g_kh[B_*H_*S_*DH_];   // K fp16
__device__ __half g_vh[B_*H_*S_*DH_];   // V fp16
__device__ float  g_att[B_*S_*D_];      // attention out [B,S,D] fp32

__device__ __forceinline__ void cvt_hilo(float x, __half& h, __half& l) {
    h = __float2half_rn(x);
    l = __float2half_rn(x - __half2float(h));
}

__device__ __forceinline__ uint32_t h2_to_u32(__half2 h) {
    union { __half2 h2; uint32_t u; } cv;
    cv.h2 = h;
    return cv.u;
}

// m16n8k16 fp16 MMA, fp32 accumulate (HMMA.16816)
__device__ __forceinline__ void mma16816(float* d, const uint32_t* a, const uint32_t* b) {
    asm volatile(
        "mma.sync.aligned.m16n8k16.row.col.f32.f16.f16.f32 "
        "{%0,%1,%2,%3}, {%4,%5,%6,%7}, {%8,%9}, {%0,%1,%2,%3};\n"
        : "+f"(d[0]), "+f"(d[1]), "+f"(d[2]), "+f"(d[3])
        : "r"(a[0]), "r"(a[1]), "r"(a[2]), "r"(a[3]), "r"(b[0]), "r"(b[1]));
}

__device__ __forceinline__ void ldsm_x4(uint32_t* r, uint32_t a) {
    asm volatile("ldmatrix.sync.aligned.m8n8.x4.shared.b16 {%0,%1,%2,%3}, [%4];"
        : "=r"(r[0]), "=r"(r[1]), "=r"(r[2]), "=r"(r[3]) : "r"(a));
}
__device__ __forceinline__ void ldsm_x4_t(uint32_t* r, uint32_t a) {
    asm volatile("ldmatrix.sync.aligned.m8n8.x4.trans.shared.b16 {%0,%1,%2,%3}, [%4];"
        : "=r"(r[0]), "=r"(r[1]), "=r"(r[2]), "=r"(r[3]) : "r"(a));
}

// =====================================================================
// GEMM common body (R12-validated structure: loads at loop top, two
// barriers, no prefetch held across MMA). 2-pass: A hi/lo, W single.
// =====================================================================
#define BKW 32
#define LDT 40
#define EPLD 36
#define GW_SMEM 73728

// Fused QKV projections: grid.z selects {Q,K,V}. Epilogue: fp16 scatter
// to [B,H,S,DH], Q additionally scaled by 0.125.
__global__ void __launch_bounds__(256) gemm_qkv(
    const float* __restrict__ Aq, const float* __restrict__ Ak,
    const float* __restrict__ Av,
    const float* __restrict__ Wq, const float* __restrict__ Wk,
    const float* __restrict__ Wv,
    const float* __restrict__ bq, const float* __restrict__ bk,
    const float* __restrict__ bv,
    __half* __restrict__ oq, __half* __restrict__ ok, __half* __restrict__ ov)
{
    extern __shared__ char smem[];
    __half* sA_hi = (__half*)smem;
    __half* sA_lo = sA_hi + 128*LDT;
    __half* sW_hi = sA_lo + 128*LDT;
    float*  sEp   = (float*)smem;

    const int z = blockIdx.z;
    const float* A    = (z == 0) ? Aq : (z == 1) ? Ak : Av;
    const float* W    = (z == 0) ? Wq : (z == 1) ? Wk : Wv;
    const float* bias = (z == 0) ? bq : (z == 1) ? bk : bv;
    __half* outh      = (z == 0) ? oq : (z == 1) ? ok : ov;
    const float sc    = (z == 0) ? 0.125f : 1.0f;

    const int tid = threadIdx.x;
    const int wid = tid >> 5, lid = tid & 31;
    const int warp_m = wid & 1;
    const int warp_n = wid >> 1;
    const int m0 = blockIdx.y * 128, n0 = blockIdx.x * 128;

    const int lrow = tid >> 3;
    const int lc4  = tid & 7;

    wmma::fragment<wmma::accumulator, 16, 16, 16, float> acc[4][2];
    #pragma unroll
    for (int m = 0; m < 4; m++)
        #pragma unroll
        for (int n = 0; n < 2; n++) wmma::fill_fragment(acc[m][n], 0.0f);

    for (int kt = 0; kt < 1024/BKW; kt++) {
        const int k0 = kt * BKW;
        float4 ra[4], rw[4];
        #pragma unroll
        for (int u = 0; u < 4; u++) {
            int row = lrow + u*32;
            ra[u] = *(const float4*)&A[(size_t)(m0 + row)*1024 + k0 + lc4*4];
            rw[u] = *(const float4*)&W[(size_t)(n0 + row)*1024 + k0 + lc4*4];
        }
        __syncthreads();

        #pragma unroll
        for (int u = 0; u < 4; u++) {
            int row = lrow + u*32;
            int off = row*LDT + lc4*4;
            __half h0,l0,h1,l1,h2,l2,h3,l3;
            cvt_hilo(ra[u].x, h0, l0); cvt_hilo(ra[u].y, h1, l1);
            cvt_hilo(ra[u].z, h2, l2); cvt_hilo(ra[u].w, h3, l3);
            ((__half2*)&sA_hi[off])[0] = __halves2half2(h0, h1);
            ((__half2*)&sA_hi[off])[1] = __halves2half2(h2, h3);
            ((__half2*)&sA_lo[off])[0] = __halves2half2(l0, l1);
            ((__half2*)&sA_lo[off])[1] = __halves2half2(l2, l3);
            h0 = __float2half_rn(rw[u].x); h1 = __float2half_rn(rw[u].y);
            h2 = __float2half_rn(rw[u].z); h3 = __float2half_rn(rw[u].w);
            ((__half2*)&sW_hi[off])[0] = __halves2half2(h0, h1);
            ((__half2*)&sW_hi[off])[1] = __halves2half2(h2, h3);
        }
        __syncthreads();

        #pragma unroll
        for (int kk = 0; kk < BKW; kk += 16) {
            wmma::fragment<wmma::matrix_a, 16, 16, 16, __half, wmma::row_major> ahi[4], alo[4];
            #pragma unroll
            for (int m = 0; m < 4; m++) {
                int r = warp_m*64 + m*16;
                wmma::load_matrix_sync(ahi[m], &sA_hi[r*LDT + kk], LDT);
                wmma::load_matrix_sync(alo[m], &sA_lo[r*LDT + kk], LDT);
            }
            #pragma unroll
            for (int n = 0; n < 2; n++) {
                int c = warp_n*32 + n*16;
                wmma::fragment<wmma::matrix_b, 16, 16, 16, __half, wmma::col_major> bhi;
                wmma::load_matrix_sync(bhi, &sW_hi[c*LDT + kk], LDT);
                #pragma unroll
                for (int m = 0; m < 4; m++) {
                    wmma::mma_sync(acc[m][n], ahi[m], bhi, acc[m][n]);
                    wmma::mma_sync(acc[m][n], alo[m], bhi, acc[m][n]);
                }
            }
        }
    }

    __syncthreads();
    float* ep = sEp + wid * 64 * EPLD;
    #pragma unroll
    for (int m = 0; m < 4; m++)
        #pragma unroll
        for (int n = 0; n < 2; n++)
            wmma::store_matrix_sync(&ep[(m*16)*EPLD + n*16], acc[m][n],
                                    EPLD, wmma::mem_row_major);
    __syncwarp();

    const int nw0 = n0 + warp_n*32;
    const int h = nw0 >> 6, d0 = nw0 & 63;
    #pragma unroll
    for (int rr = 0; rr < 2; rr++) {
        int r = lid + rr*32;
        int gm = m0 + warp_m*64 + r;
        int b = gm >> 11, s = gm & 2047;
        size_t base = (((size_t)(b*H_ + h))*S_ + s)*DH_ + d0;
        #pragma unroll
        for (int c4 = 0; c4 < 8; c4++) {
            float4 v = *(float4*)&ep[r*EPLD + c4*4];
            int n = nw0 + c4*4;
            v.x = (v.x + bias[n+0]) * sc;
            v.y = (v.y + bias[n+1]) * sc;
            v.z = (v.z + bias[n+2]) * sc;
            v.w = (v.w + bias[n+3]) * sc;
            uint2 hv = make_uint2(h2_to_u32(__floats2half2_rn(v.x, v.y)),
                                  h2_to_u32(__floats2half2_rn(v.z, v.w)));
            *(uint2*)&outh[base + c4*4] = hv;
        }
    }
}

// O-projection: fp32 A (g_att), 2-pass A hi/lo, fp32 out. R12-identical.
__global__ void __launch_bounds__(256) gemm_o(
    const float* __restrict__ A, const float* __restrict__ W,
    const float* __restrict__ bias, float* __restrict__ outf)
{
    extern __shared__ char smem[];
    __half* sA_hi = (__half*)smem;
    __half* sA_lo = sA_hi + 128*LDT;
    __half* sW_hi = sA_lo + 128*LDT;
    float*  sEp   = (float*)smem;

    const int tid = threadIdx.x;
    const int wid = tid >> 5, lid = tid & 31;
    const int warp_m = wid & 1;
    const int warp_n = wid >> 1;
    const int m0 = blockIdx.y * 128, n0 = blockIdx.x * 128;

    const int lrow = tid >> 3;
    const int lc4  = tid & 7;

    wmma::fragment<wmma::accumulator, 16, 16, 16, float> acc[4][2];
    #pragma unroll
    for (int m = 0; m < 4; m++)
        #pragma unroll
        for (int n = 0; n < 2; n++) wmma::fill_fragment(acc[m][n], 0.0f);

    for (int kt = 0; kt < 1024/BKW; kt++) {
        const int k0 = kt * BKW;
        float4 ra[4], rw[4];
        #pragma unroll
        for (int u = 0; u < 4; u++) {
            int row = lrow + u*32;
            ra[u] = *(const float4*)&A[(size_t)(m0 + row)*1024 + k0 + lc4*4];
            rw[u] = *(const float4*)&W[(size_t)(n0 + row)*1024 + k0 + lc4*4];
        }
        __syncthreads();

        #pragma unroll
        for (int u = 0; u < 4; u++) {
            int row = lrow + u*32;
            int off = row*LDT + lc4*4;
            __half h0,l0,h1,l1,h2,l2,h3,l3;
            cvt_hilo(ra[u].x, h0, l0); cvt_hilo(ra[u].y, h1, l1);
            cvt_hilo(ra[u].z, h2, l2); cvt_hilo(ra[u].w, h3, l3);
            ((__half2*)&sA_hi[off])[0] = __halves2half2(h0, h1);
            ((__half2*)&sA_hi[off])[1] = __halves2half2(h2, h3);
            ((__half2*)&sA_lo[off])[0] = __halves2half2(l0, l1);
            ((__half2*)&sA_lo[off])[1] = __halves2half2(l2, l3);
            h0 = __float2half_rn(rw[u].x); h1 = __float2half_rn(rw[u].y);
            h2 = __float2half_rn(rw[u].z); h3 = __float2half_rn(rw[u].w);
            ((__half2*)&sW_hi[off])[0] = __halves2half2(h0, h1);
            ((__half2*)&sW_hi[off])[1] = __halves2half2(h2, h3);
        }
        __syncthreads();

        #pragma unroll
        for (int kk = 0; kk < BKW; kk += 16) {
            wmma::fragment<wmma::matrix_a, 16, 16, 16, __half, wmma::row_major> ahi[4], alo[4];
            #pragma unroll
            for (int m = 0; m < 4; m++) {
                int r = warp_m*64 + m*16;
                wmma::load_matrix_sync(ahi[m], &sA_hi[r*LDT + kk], LDT);
                wmma::load_matrix_sync(alo[m], &sA_lo[r*LDT + kk], LDT);
            }
            #pragma unroll
            for (int n = 0; n < 2; n++) {
                int c = warp_n*32 + n*16;
                wmma::fragment<wmma::matrix_b, 16, 16, 16, __half, wmma::col_major> bhi;
                wmma::load_matrix_sync(bhi, &sW_hi[c*LDT + kk], LDT);
                #pragma unroll
                for (int m = 0; m < 4; m++) {
                    wmma::mma_sync(acc[m][n], ahi[m], bhi, acc[m][n]);
                    wmma::mma_sync(acc[m][n], alo[m], bhi, acc[m][n]);
                }
            }
        }
    }

    __syncthreads();
    float* ep = sEp + wid * 64 * EPLD;
    #pragma unroll
    for (int m = 0; m < 4; m++)
        #pragma unroll
        for (int n = 0; n < 2; n++)
            wmma::store_matrix_sync(&ep[(m*16)*EPLD + n*16], acc[m][n],
                                    EPLD, wmma::mem_row_major);
    __syncwarp();

    const int nw0 = n0 + warp_n*32;
    #pragma unroll
    for (int rr = 0; rr < 2; rr++) {
        int r = lid + rr*32;
        int gm = m0 + warp_m*64 + r;
        #pragma unroll
        for (int c4 = 0; c4 < 8; c4++) {
            float4 v = *(float4*)&ep[r*EPLD + c4*4];
            int n = nw0 + c4*4;
            v.x += bias[n+0]; v.y += bias[n+1];
            v.z += bias[n+2]; v.w += bias[n+3];
            *(float4*)&outf[(size_t)gm*1024 + n] = v;
        }
    }
}

// =====================================================================
// Flash attention — raw mma.sync + ldmatrix; Q,K,V all single fp16
// (Q pre-scaled). QK^T single-pass, PV single-pass. 128 MMAs/tile.
// =====================================================================
#define TLD 72          // leading dim (halves); 144B rows

#define AT_Q 0
#define AT_K (AT_Q + 128*TLD*2)          // 18432
#define AT_V (AT_K + 128*TLD*2)          // 36864
#define ATT_SMEM (AT_V + 128*TLD*2)      // 55296

__global__ void __launch_bounds__(256, 1) attn_mma()
{
    extern __shared__ char smem[];
    __half* Qs = (__half*)(smem + AT_Q);
    __half* Ks = (__half*)(smem + AT_K);
    __half* Vs = (__half*)(smem + AT_V);

    const int tid = threadIdx.x;
    const int wid = tid >> 5;
    const int lane = tid & 31;
    const int m0 = wid * 16;
    const int bh = blockIdx.y;
    const int q0 = blockIdx.x * 128;

    const __half* qbase = g_qh + (size_t)bh*S_*DH_;
    const __half* kbase = g_kh + (size_t)bh*S_*DH_;
    const __half* vbase = g_vh + (size_t)bh*S_*DH_;

    const int lrow = tid >> 3;
    const int lcu  = tid & 7;

    const uint32_t sb = (uint32_t)__cvta_generic_to_shared(smem);
    const int li = lane >> 3;
    const int l7 = lane & 7;
    const uint32_t aQ = sb + AT_Q +
        ((uint32_t)((m0 + ((li & 1) << 3) + l7) * TLD + ((li >> 1) << 3)) << 1);
    const uint32_t aK = sb + AT_K +
        ((uint32_t)((((li >> 1) << 3) + l7) * TLD + ((li & 1) << 3)) << 1);
    const uint32_t aV = sb + AT_V +
        ((uint32_t)((((li & 1) << 3) + l7) * TLD + ((li >> 1) << 3)) << 1);

    #pragma unroll
    for (int u = 0; u < 4; u++) {
        int row = lrow + u*32;
        uint4 vq = *(const uint4*)&qbase[(size_t)(q0 + row)*DH_ + lcu*8];
        *(uint4*)&Qs[row*TLD + lcu*8] = vq;
    }

    float O[8][4];
    #pragma unroll
    for (int n = 0; n < 8; n++)
        #pragma unroll
        for (int t = 0; t < 4; t++) O[n][t] = 0.f;
    float mr0 = -INFINITY, mr1 = -INFINITY;
    float lr0 = 0.f, lr1 = 0.f;

    for (int kt = 0; kt < S_/128; kt++) {
        const int k0g = kt * 128;
        uint4 rk[4], rv[4];
        #pragma unroll
        for (int u = 0; u < 4; u++) {
            int row = lrow + u*32;
            rk[u] = *(const uint4*)&kbase[(size_t)(k0g + row)*DH_ + lcu*8];
            rv[u] = *(const uint4*)&vbase[(size_t)(k0g + row)*DH_ + lcu*8];
        }
        __syncthreads();
        #pragma unroll
        for (int u = 0; u < 4; u++) {
            int row = lrow + u*32;
            *(uint4*)&Ks[row*TLD + lcu*8] = rk[u];
            *(uint4*)&Vs[row*TLD + lcu*8] = rv[u];
        }
        __syncthreads();

        float sacc[16][4];
        #pragma unroll
        for (int n = 0; n < 16; n++)
            #pragma unroll
            for (int t = 0; t < 4; t++) sacc[n][t] = 0.f;

        #pragma unroll
        for (int kk = 0; kk < 64; kk += 16) {
            uint32_t qf[4];
            ldsm_x4(qf, aQ + (kk << 1));
            #pragma unroll
            for (int np = 0; np < 8; np++) {
                uint32_t kf[4];
                ldsm_x4(kf, aK + ((np*16*TLD + kk) << 1));
                mma16816(sacc[2*np],   qf, kf);
                mma16816(sacc[2*np+1], qf, kf + 2);
            }
        }

        float mx0 = -INFINITY, mx1 = -INFINITY;
        #pragma unroll
        for (int n = 0; n < 16; n++) {
            mx0 = fmaxf(mx0, fmaxf(sacc[n][0], sacc[n][1]));
            mx1 = fmaxf(mx1, fmaxf(sacc[n][2], sacc[n][3]));
        }
        mx0 = fmaxf(mx0, __shfl_xor_sync(0xffffffffu, mx0, 1));
        mx0 = fmaxf(mx0, __shfl_xor_sync(0xffffffffu, mx0, 2));
        mx1 = fmaxf(mx1, __shfl_xor_sync(0xffffffffu, mx1, 1));
        mx1 = fmaxf(mx1, __shfl_xor_sync(0xffffffffu, mx1, 2));
        float m0n = fmaxf(mr0, mx0), m1n = fmaxf(mr1, mx1);
        float al0 = __expf(mr0 - m0n), al1 = __expf(mr1 - m1n);
        mr0 = m0n; mr1 = m1n;

        uint32_t pa[8][4];
        float sum0 = 0.f, sum1 = 0.f;
        #pragma unroll
        for (int j = 0; j < 8; j++) {
            float p00 = __expf(sacc[2*j][0] - m0n);
            float p01 = __expf(sacc[2*j][1] - m0n);
            float p10 = __expf(sacc[2*j][2] - m1n);
            float p11 = __expf(sacc[2*j][3] - m1n);
            float p04 = __expf(sacc[2*j+1][0] - m0n);
            float p05 = __expf(sacc[2*j+1][1] - m0n);
            float p14 = __expf(sacc[2*j+1][2] - m1n);
            float p15 = __expf(sacc[2*j+1][3] - m1n);
            sum0 += p00 + p01 + p04 + p05;
            sum1 += p10 + p11 + p14 + p15;
            pa[j][0] = h2_to_u32(__floats2half2_rn(p00, p01));
            pa[j][1] = h2_to_u32(__floats2half2_rn(p10, p11));
            pa[j][2] = h2_to_u32(__floats2half2_rn(p04, p05));
            pa[j][3] = h2_to_u32(__floats2half2_rn(p14, p15));
        }
        sum0 += __shfl_xor_sync(0xffffffffu, sum0, 1);
        sum0 += __shfl_xor_sync(0xffffffffu, sum0, 2);
        sum1 += __shfl_xor_sync(0xffffffffu, sum1, 1);
        sum1 += __shfl_xor_sync(0xffffffffu, sum1, 2);
        lr0 = lr0*al0 + sum0;
        lr1 = lr1*al1 + sum1;

        #pragma unroll
        for (int n = 0; n < 8; n++) {
            O[n][0] *= al0; O[n][1] *= al0;
            O[n][2] *= al1; O[n][3] *= al1;
        }
        #pragma unroll
        for (int j = 0; j < 8; j++) {
            #pragma unroll
            for (int nvp = 0; nvp < 4; nvp++) {
                uint32_t vf[4];
                ldsm_x4_t(vf, aV + ((j*16*TLD + nvp*16) << 1));
                mma16816(O[2*nvp],   pa[j], vf);
                mma16816(O[2*nvp+1], pa[j], vf + 2);
            }
        }
    }

    // ---- normalize + write [B,S,D] ----
    const int g = lane >> 2;
    const int c = lane & 3;
    const int b = bh >> 4, h = bh & 15;
    float il0 = 1.0f / lr0, il1 = 1.0f / lr1;
    const int r0 = q0 + m0 + g, r1 = r0 + 8;
    #pragma unroll
    for (int nv = 0; nv < 8; nv++) {
        int col = h*DH_ + nv*8 + 2*c;
        float2 v0 = make_float2(O[nv][0]*il0, O[nv][1]*il0);
        float2 v1 = make_float2(O[nv][2]*il1, O[nv][3]*il1);
        *(float2*)&g_att[((size_t)(b*S_ + r0))*D_ + col] = v0;
        *(float2*)&g_att[((size_t)(b*S_ + r1))*D_ + col] = v1;
    }
}

// =====================================================================
// Launch
// =====================================================================
extern "C" void kernel_launch(void* const* d_in, const int* in_sizes, int n_in,
                              void* d_out, int out_size)
{
    const float* query  = (const float*)d_in[0];
    const float* keys   = (const float*)d_in[1];
    const float* values = (const float*)d_in[2];
    const float* Wq = (const float*)d_in[3];
    const float* bq = (const float*)d_in[4];
    const float* Wk = (const float*)d_in[5];
    const float* bk = (const float*)d_in[6];
    const float* Wv = (const float*)d_in[7];
    const float* bv = (const float*)d_in[8];
    const float* Wo = (const float*)d_in[9];
    const float* bo = (const float*)d_in[10];
    float* out = (float*)d_out;

    __half *qhp, *khp, *vhp;
    float *ap;
    cudaGetSymbolAddress((void**)&qhp, g_qh);
    cudaGetSymbolAddress((void**)&khp, g_kh);
    cudaGetSymbolAddress((void**)&vhp, g_vh);
    cudaGetSymbolAddress((void**)&ap,  g_att);

    cudaFuncSetAttribute(gemm_qkv,
                         cudaFuncAttributeMaxDynamicSharedMemorySize, GW_SMEM);
    cudaFuncSetAttribute(gemm_o,
                         cudaFuncAttributeMaxDynamicSharedMemorySize, GW_SMEM);
    cudaFuncSetAttribute(attn_mma,
                         cudaFuncAttributeMaxDynamicSharedMemorySize, ATT_SMEM);

    // fused QKV: 768 CTAs in one launch (wave smoothing)
    gemm_qkv<<<dim3(D_/128, M_/128, 3), 256, GW_SMEM>>>(
        query, keys, values, Wq, Wk, Wv, bq, bk, bv, qhp, khp, vhp);

    attn_mma<<<dim3(S_/128, B_*H_), 256, ATT_SMEM>>>();

    gemm_o<<<dim3(D_/128, M_/128), 256, GW_SMEM>>>(ap, Wo, bo, out);
}

// round 16
// speedup vs baseline: 1.4904x; 1.1614x over previous
#include <cuda_runtime.h>
#include <cuda_fp16.h>
#include <mma.h>
#include <math.h>
#include <stdint.h>

using namespace nvcuda;

// Problem constants
#define B_   2
#define S_   2048
#define D_   1024
#define H_   16
#define DH_  64
#define M_   (B_*S_)

// ---------------- scratch (device globals; no allocation) ----------------
__device__ __half g_qh[B_*H_*S_*DH_];   // Q fp16 (pre-scaled by 0.125)
__device__ __half g_kh[B_*H_*S_*DH_];   // K fp16
__device__ __half g_vh[B_*H_*S_*DH_];   // V fp16
__device__ float  g_att[B_*S_*D_];      // attention out [B,S,D] fp32

__device__ __forceinline__ uint32_t h2_to_u32(__half2 h) {
    union { __half2 h2; uint32_t u; } cv;
    cv.h2 = h;
    return cv.u;
}

// m16n8k16 fp16 MMA, fp32 accumulate (HMMA.16816)
__device__ __forceinline__ void mma16816(float* d, const uint32_t* a, const uint32_t* b) {
    asm volatile(
        "mma.sync.aligned.m16n8k16.row.col.f32.f16.f16.f32 "
        "{%0,%1,%2,%3}, {%4,%5,%6,%7}, {%8,%9}, {%0,%1,%2,%3};\n"
        : "+f"(d[0]), "+f"(d[1]), "+f"(d[2]), "+f"(d[3])
        : "r"(a[0]), "r"(a[1]), "r"(a[2]), "r"(a[3]), "r"(b[0]), "r"(b[1]));
}

__device__ __forceinline__ void ldsm_x4(uint32_t* r, uint32_t a) {
    asm volatile("ldmatrix.sync.aligned.m8n8.x4.shared.b16 {%0,%1,%2,%3}, [%4];"
        : "=r"(r[0]), "=r"(r[1]), "=r"(r[2]), "=r"(r[3]) : "r"(a));
}
__device__ __forceinline__ void ldsm_x4_t(uint32_t* r, uint32_t a) {
    asm volatile("ldmatrix.sync.aligned.m8n8.x4.trans.shared.b16 {%0,%1,%2,%3}, [%4];"
        : "=r"(r[0]), "=r"(r[1]), "=r"(r[2]), "=r"(r[3]) : "r"(a));
}

// =====================================================================
// Single-pass fp16 GEMM (A and W both single-rounded fp16).
// Error budget (calibrated R10->R11): each rounding term ~0.65e-4 RSS;
// predicted total ~2.1e-4 vs 1e-3 gate.
// Structure identical to R12/R15 validated body, minus the A-lo pass.
// =====================================================================
#define BKW 32
#define LDT 40
#define EPLD 36
#define GW_SMEM 73728   // 3*128*LDT*2 = 30720 operands; epilogue 73728 (union)

// Fused QKV projections: grid.z selects {Q,K,V}. Epilogue: fp16 scatter
// to [B,H,S,DH], Q additionally scaled by 0.125.
__global__ void __launch_bounds__(256) gemm_qkv(
    const float* __restrict__ Aq, const float* __restrict__ Ak,
    const float* __restrict__ Av,
    const float* __restrict__ Wq, const float* __restrict__ Wk,
    const float* __restrict__ Wv,
    const float* __restrict__ bq, const float* __restrict__ bk,
    const float* __restrict__ bv,
    __half* __restrict__ oq, __half* __restrict__ ok, __half* __restrict__ ov)
{
    extern __shared__ char smem[];
    __half* sA = (__half*)smem;
    __half* sW = sA + 128*LDT;
    float*  sEp = (float*)smem;

    const int z = blockIdx.z;
    const float* A    = (z == 0) ? Aq : (z == 1) ? Ak : Av;
    const float* W    = (z == 0) ? Wq : (z == 1) ? Wk : Wv;
    const float* bias = (z == 0) ? bq : (z == 1) ? bk : bv;
    __half* outh      = (z == 0) ? oq : (z == 1) ? ok : ov;
    const float sc    = (z == 0) ? 0.125f : 1.0f;

    const int tid = threadIdx.x;
    const int wid = tid >> 5, lid = tid & 31;
    const int warp_m = wid & 1;
    const int warp_n = wid >> 1;
    const int m0 = blockIdx.y * 128, n0 = blockIdx.x * 128;

    const int lrow = tid >> 3;
    const int lc4  = tid & 7;

    wmma::fragment<wmma::accumulator, 16, 16, 16, float> acc[4][2];
    #pragma unroll
    for (int m = 0; m < 4; m++)
        #pragma unroll
        for (int n = 0; n < 2; n++) wmma::fill_fragment(acc[m][n], 0.0f);

    for (int kt = 0; kt < 1024/BKW; kt++) {
        const int k0 = kt * BKW;
        float4 ra[4], rw[4];
        #pragma unroll
        for (int u = 0; u < 4; u++) {
            int row = lrow + u*32;
            ra[u] = *(const float4*)&A[(size_t)(m0 + row)*1024 + k0 + lc4*4];
            rw[u] = *(const float4*)&W[(size_t)(n0 + row)*1024 + k0 + lc4*4];
        }
        __syncthreads();

        #pragma unroll
        for (int u = 0; u < 4; u++) {
            int row = lrow + u*32;
            int off = row*LDT + lc4*4;
            ((__half2*)&sA[off])[0] = __floats2half2_rn(ra[u].x, ra[u].y);
            ((__half2*)&sA[off])[1] = __floats2half2_rn(ra[u].z, ra[u].w);
            ((__half2*)&sW[off])[0] = __floats2half2_rn(rw[u].x, rw[u].y);
            ((__half2*)&sW[off])[1] = __floats2half2_rn(rw[u].z, rw[u].w);
        }
        __syncthreads();

        #pragma unroll
        for (int kk = 0; kk < BKW; kk += 16) {
            wmma::fragment<wmma::matrix_a, 16, 16, 16, __half, wmma::row_major> af[4];
            #pragma unroll
            for (int m = 0; m < 4; m++) {
                int r = warp_m*64 + m*16;
                wmma::load_matrix_sync(af[m], &sA[r*LDT + kk], LDT);
            }
            #pragma unroll
            for (int n = 0; n < 2; n++) {
                int c = warp_n*32 + n*16;
                wmma::fragment<wmma::matrix_b, 16, 16, 16, __half, wmma::col_major> bf;
                wmma::load_matrix_sync(bf, &sW[c*LDT + kk], LDT);
                #pragma unroll
                for (int m = 0; m < 4; m++)
                    wmma::mma_sync(acc[m][n], af[m], bf, acc[m][n]);
            }
        }
    }

    __syncthreads();
    float* ep = sEp + wid * 64 * EPLD;
    #pragma unroll
    for (int m = 0; m < 4; m++)
        #pragma unroll
        for (int n = 0; n < 2; n++)
            wmma::store_matrix_sync(&ep[(m*16)*EPLD + n*16], acc[m][n],
                                    EPLD, wmma::mem_row_major);
    __syncwarp();

    const int nw0 = n0 + warp_n*32;
    const int h = nw0 >> 6, d0 = nw0 & 63;
    #pragma unroll
    for (int rr = 0; rr < 2; rr++) {
        int r = lid + rr*32;
        int gm = m0 + warp_m*64 + r;
        int b = gm >> 11, s = gm & 2047;
        size_t base = (((size_t)(b*H_ + h))*S_ + s)*DH_ + d0;
        #pragma unroll
        for (int c4 = 0; c4 < 8; c4++) {
            float4 v = *(float4*)&ep[r*EPLD + c4*4];
            int n = nw0 + c4*4;
            v.x = (v.x + bias[n+0]) * sc;
            v.y = (v.y + bias[n+1]) * sc;
            v.z = (v.z + bias[n+2]) * sc;
            v.w = (v.w + bias[n+3]) * sc;
            uint2 hv = make_uint2(h2_to_u32(__floats2half2_rn(v.x, v.y)),
                                  h2_to_u32(__floats2half2_rn(v.z, v.w)));
            *(uint2*)&outh[base + c4*4] = hv;
        }
    }
}

// O-projection: single-pass fp16, fp32 out.
__global__ void __launch_bounds__(256) gemm_o(
    const float* __restrict__ A, const float* __restrict__ W,
    const float* __restrict__ bias, float* __restrict__ outf)
{
    extern __shared__ char smem[];
    __half* sA = (__half*)smem;
    __half* sW = sA + 128*LDT;
    float*  sEp = (float*)smem;

    const int tid = threadIdx.x;
    const int wid = tid >> 5, lid = tid & 31;
    const int warp_m = wid & 1;
    const int warp_n = wid >> 1;
    const int m0 = blockIdx.y * 128, n0 = blockIdx.x * 128;

    const int lrow = tid >> 3;
    const int lc4  = tid & 7;

    wmma::fragment<wmma::accumulator, 16, 16, 16, float> acc[4][2];
    #pragma unroll
    for (int m = 0; m < 4; m++)
        #pragma unroll
        for (int n = 0; n < 2; n++) wmma::fill_fragment(acc[m][n], 0.0f);

    for (int kt = 0; kt < 1024/BKW; kt++) {
        const int k0 = kt * BKW;
        float4 ra[4], rw[4];
        #pragma unroll
        for (int u = 0; u < 4; u++) {
            int row = lrow + u*32;
            ra[u] = *(const float4*)&A[(size_t)(m0 + row)*1024 + k0 + lc4*4];
            rw[u] = *(const float4*)&W[(size_t)(n0 + row)*1024 + k0 + lc4*4];
        }
        __syncthreads();

        #pragma unroll
        for (int u = 0; u < 4; u++) {
            int row = lrow + u*32;
            int off = row*LDT + lc4*4;
            ((__half2*)&sA[off])[0] = __floats2half2_rn(ra[u].x, ra[u].y);
            ((__half2*)&sA[off])[1] = __floats2half2_rn(ra[u].z, ra[u].w);
            ((__half2*)&sW[off])[0] = __floats2half2_rn(rw[u].x, rw[u].y);
            ((__half2*)&sW[off])[1] = __floats2half2_rn(rw[u].z, rw[u].w);
        }
        __syncthreads();

        #pragma unroll
        for (int kk = 0; kk < BKW; kk += 16) {
            wmma::fragment<wmma::matrix_a, 16, 16, 16, __half, wmma::row_major> af[4];
            #pragma unroll
            for (int m = 0; m < 4; m++) {
                int r = warp_m*64 + m*16;
                wmma::load_matrix_sync(af[m], &sA[r*LDT + kk], LDT);
            }
            #pragma unroll
            for (int n = 0; n < 2; n++) {
                int c = warp_n*32 + n*16;
                wmma::fragment<wmma::matrix_b, 16, 16, 16, __half, wmma::col_major> bf;
                wmma::load_matrix_sync(bf, &sW[c*LDT + kk], LDT);
                #pragma unroll
                for (int m = 0; m < 4; m++)
                    wmma::mma_sync(acc[m][n], af[m], bf, acc[m][n]);
            }
        }
    }

    __syncthreads();
    float* ep = sEp + wid * 64 * EPLD;
    #pragma unroll
    for (int m = 0; m < 4; m++)
        #pragma unroll
        for (int n = 0; n < 2; n++)
            wmma::store_matrix_sync(&ep[(m*16)*EPLD + n*16], acc[m][n],
                                    EPLD, wmma::mem_row_major);
    __syncwarp();

    const int nw0 = n0 + warp_n*32;
    #pragma unroll
    for (int rr = 0; rr < 2; rr++) {
        int r = lid + rr*32;
        int gm = m0 + warp_m*64 + r;
        #pragma unroll
        for (int c4 = 0; c4 < 8; c4++) {
            float4 v = *(float4*)&ep[r*EPLD + c4*4];
            int n = nw0 + c4*4;
            v.x += bias[n+0]; v.y += bias[n+1];
            v.z += bias[n+2]; v.w += bias[n+3];
            *(float4*)&outf[(size_t)gm*1024 + n] = v;
        }
    }
}

// =====================================================================
// Flash attention — unchanged from R15 (validated ~158us).
// Q,K,V single fp16 (Q pre-scaled). QK^T and PV single-pass.
// =====================================================================
#define TLD 72          // leading dim (halves); 144B rows

#define AT_Q 0
#define AT_K (AT_Q + 128*TLD*2)          // 18432
#define AT_V (AT_K + 128*TLD*2)          // 36864
#define ATT_SMEM (AT_V + 128*TLD*2)      // 55296

__global__ void __launch_bounds__(256, 1) attn_mma()
{
    extern __shared__ char smem[];
    __half* Qs = (__half*)(smem + AT_Q);
    __half* Ks = (__half*)(smem + AT_K);
    __half* Vs = (__half*)(smem + AT_V);

    const int tid = threadIdx.x;
    const int wid = tid >> 5;
    const int lane = tid & 31;
    const int m0 = wid * 16;
    const int bh = blockIdx.y;
    const int q0 = blockIdx.x * 128;

    const __half* qbase = g_qh + (size_t)bh*S_*DH_;
    const __half* kbase = g_kh + (size_t)bh*S_*DH_;
    const __half* vbase = g_vh + (size_t)bh*S_*DH_;

    const int lrow = tid >> 3;
    const int lcu  = tid & 7;

    const uint32_t sb = (uint32_t)__cvta_generic_to_shared(smem);
    const int li = lane >> 3;
    const int l7 = lane & 7;
    const uint32_t aQ = sb + AT_Q +
        ((uint32_t)((m0 + ((li & 1) << 3) + l7) * TLD + ((li >> 1) << 3)) << 1);
    const uint32_t aK = sb + AT_K +
        ((uint32_t)((((li >> 1) << 3) + l7) * TLD + ((li & 1) << 3)) << 1);
    const uint32_t aV = sb + AT_V +
        ((uint32_t)((((li & 1) << 3) + l7) * TLD + ((li >> 1) << 3)) << 1);

    #pragma unroll
    for (int u = 0; u < 4; u++) {
        int row = lrow + u*32;
        uint4 vq = *(const uint4*)&qbase[(size_t)(q0 + row)*DH_ + lcu*8];
        *(uint4*)&Qs[row*TLD + lcu*8] = vq;
    }

    float O[8][4];
    #pragma unroll
    for (int n = 0; n < 8; n++)
        #pragma unroll
        for (int t = 0; t < 4; t++) O[n][t] = 0.f;
    float mr0 = -INFINITY, mr1 = -INFINITY;
    float lr0 = 0.f, lr1 = 0.f;

    for (int kt = 0; kt < S_/128; kt++) {
        const int k0g = kt * 128;
        uint4 rk[4], rv[4];
        #pragma unroll
        for (int u = 0; u < 4; u++) {
            int row = lrow + u*32;
            rk[u] = *(const uint4*)&kbase[(size_t)(k0g + row)*DH_ + lcu*8];
            rv[u] = *(const uint4*)&vbase[(size_t)(k0g + row)*DH_ + lcu*8];
        }
        __syncthreads();
        #pragma unroll
        for (int u = 0; u < 4; u++) {
            int row = lrow + u*32;
            *(uint4*)&Ks[row*TLD + lcu*8] = rk[u];
            *(uint4*)&Vs[row*TLD + lcu*8] = rv[u];
        }
        __syncthreads();

        float sacc[16][4];
        #pragma unroll
        for (int n = 0; n < 16; n++)
            #pragma unroll
            for (int t = 0; t < 4; t++) sacc[n][t] = 0.f;

        #pragma unroll
        for (int kk = 0; kk < 64; kk += 16) {
            uint32_t qf[4];
            ldsm_x4(qf, aQ + (kk << 1));
            #pragma unroll
            for (int np = 0; np < 8; np++) {
                uint32_t kf[4];
                ldsm_x4(kf, aK + ((np*16*TLD + kk) << 1));
                mma16816(sacc[2*np],   qf, kf);
                mma16816(sacc[2*np+1], qf, kf + 2);
            }
        }

        float mx0 = -INFINITY, mx1 = -INFINITY;
        #pragma unroll
        for (int n = 0; n < 16; n++) {
            mx0 = fmaxf(mx0, fmaxf(sacc[n][0], sacc[n][1]));
            mx1 = fmaxf(mx1, fmaxf(sacc[n][2], sacc[n][3]));
        }
        mx0 = fmaxf(mx0, __shfl_xor_sync(0xffffffffu, mx0, 1));
        mx0 = fmaxf(mx0, __shfl_xor_sync(0xffffffffu, mx0, 2));
        mx1 = fmaxf(mx1, __shfl_xor_sync(0xffffffffu, mx1, 1));
        mx1 = fmaxf(mx1, __shfl_xor_sync(0xffffffffu, mx1, 2));
        float m0n = fmaxf(mr0, mx0), m1n = fmaxf(mr1, mx1);
        float al0 = __expf(mr0 - m0n), al1 = __expf(mr1 - m1n);
        mr0 = m0n; mr1 = m1n;

        uint32_t pa[8][4];
        float sum0 = 0.f, sum1 = 0.f;
        #pragma unroll
        for (int j = 0; j < 8; j++) {
            float p00 = __expf(sacc[2*j][0] - m0n);
            float p01 = __expf(sacc[2*j][1] - m0n);
            float p10 = __expf(sacc[2*j][2] - m1n);
            float p11 = __expf(sacc[2*j][3] - m1n);
            float p04 = __expf(sacc[2*j+1][0] - m0n);
            float p05 = __expf(sacc[2*j+1][1] - m0n);
            float p14 = __expf(sacc[2*j+1][2] - m1n);
            float p15 = __expf(sacc[2*j+1][3] - m1n);
            sum0 += p00 + p01 + p04 + p05;
            sum1 += p10 + p11 + p14 + p15;
            pa[j][0] = h2_to_u32(__floats2half2_rn(p00, p01));
            pa[j][1] = h2_to_u32(__floats2half2_rn(p10, p11));
            pa[j][2] = h2_to_u32(__floats2half2_rn(p04, p05));
            pa[j][3] = h2_to_u32(__floats2half2_rn(p14, p15));
        }
        sum0 += __shfl_xor_sync(0xffffffffu, sum0, 1);
        sum0 += __shfl_xor_sync(0xffffffffu, sum0, 2);
        sum1 += __shfl_xor_sync(0xffffffffu, sum1, 1);
        sum1 += __shfl_xor_sync(0xffffffffu, sum1, 2);
        lr0 = lr0*al0 + sum0;
        lr1 = lr1*al1 + sum1;

        #pragma unroll
        for (int n = 0; n < 8; n++) {
            O[n][0] *= al0; O[n][1] *= al0;
            O[n][2] *= al1; O[n][3] *= al1;
        }
        #pragma unroll
        for (int j = 0; j < 8; j++) {
            #pragma unroll
            for (int nvp = 0; nvp < 4; nvp++) {
                uint32_t vf[4];
                ldsm_x4_t(vf, aV + ((j*16*TLD + nvp*16) << 1));
                mma16816(O[2*nvp],   pa[j], vf);
                mma16816(O[2*nvp+1], pa[j], vf + 2);
            }
        }
    }

    // ---- normalize + write [B,S,D] ----
    const int g = lane >> 2;
    const int c = lane & 3;
    const int b = bh >> 4, h = bh & 15;
    float il0 = 1.0f / lr0, il1 = 1.0f / lr1;
    const int r0 = q0 + m0 + g, r1 = r0 + 8;
    #pragma unroll
    for (int nv = 0; nv < 8; nv++) {
        int col = h*DH_ + nv*8 + 2*c;
        float2 v0 = make_float2(O[nv][0]*il0, O[nv][1]*il0);
        float2 v1 = make_float2(O[nv][2]*il1, O[nv][3]*il1);
        *(float2*)&g_att[((size_t)(b*S_ + r0))*D_ + col] = v0;
        *(float2*)&g_att[((size_t)(b*S_ + r1))*D_ + col] = v1;
    }
}

// =====================================================================
// Launch
// =====================================================================
extern "C" void kernel_launch(void* const* d_in, const int* in_sizes, int n_in,
                              void* d_out, int out_size)
{
    const float* query  = (const float*)d_in[0];
    const float* keys   = (const float*)d_in[1];
    const float* values = (const float*)d_in[2];
    const float* Wq = (const float*)d_in[3];
    const float* bq = (const float*)d_in[4];
    const float* Wk = (const float*)d_in[5];
    const float* bk = (const float*)d_in[6];
    const float* Wv = (const float*)d_in[7];
    const float* bv = (const float*)d_in[8];
    const float* Wo = (const float*)d_in[9];
    const float* bo = (const float*)d_in[10];
    float* out = (float*)d_out;

    __half *qhp, *khp, *vhp;
    float *ap;
    cudaGetSymbolAddress((void**)&qhp, g_qh);
    cudaGetSymbolAddress((void**)&khp, g_kh);
    cudaGetSymbolAddress((void**)&vhp, g_vh);
    cudaGetSymbolAddress((void**)&ap,  g_att);

    cudaFuncSetAttribute(gemm_qkv,
                         cudaFuncAttributeMaxDynamicSharedMemorySize, GW_SMEM);
    cudaFuncSetAttribute(gemm_o,
                         cudaFuncAttributeMaxDynamicSharedMemorySize, GW_SMEM);
    cudaFuncSetAttribute(attn_mma,
                         cudaFuncAttributeMaxDynamicSharedMemorySize, ATT_SMEM);

    // fused QKV: 768 CTAs in one launch (wave smoothing)
    gemm_qkv<<<dim3(D_/128, M_/128, 3), 256, GW_SMEM>>>(
        query, keys, values, Wq, Wk, Wv, bq, bk, bv, qhp, khp, vhp);

    attn_mma<<<dim3(S_/128, B_*H_), 256, ATT_SMEM>>>();

    gemm_o<<<dim3(D_/128, M_/128), 256, GW_SMEM>>>(ap, Wo, bo, out);
}

// round 17
// speedup vs baseline: 1.7008x; 1.1411x over previous
#include <cuda_runtime.h>
#include <cuda_fp16.h>
#include <math.h>
#include <stdint.h>

// Problem constants
#define B_   2
#define S_   2048
#define D_   1024
#define H_   16
#define DH_  64
#define M_   (B_*S_)

// ---------------- scratch (device globals; no allocation) ----------------
__device__ __half g_qin[M_*D_];         // query activations fp16
__device__ __half g_kin[M_*D_];         // keys activations fp16
__device__ __half g_vin[M_*D_];         // values activations fp16
__device__ __half g_w[4*D_*D_];         // Wq,Wk,Wv,Wo fp16
__device__ __half g_qh[B_*H_*S_*DH_];   // Q fp16 (pre-scaled by 0.125)
__device__ __half g_kh[B_*H_*S_*DH_];   // K fp16
__device__ __half g_vh[B_*H_*S_*DH_];   // V fp16
__device__ __half g_atth[M_*D_];        // attention out fp16 [B,S,D]

__device__ __forceinline__ uint32_t h2_to_u32(__half2 h) {
    union { __half2 h2; uint32_t u; } cv;
    cv.h2 = h;
    return cv.u;
}

// m16n8k16 fp16 MMA, fp32 accumulate (HMMA.16816)
__device__ __forceinline__ void mma16816(float* d, const uint32_t* a, const uint32_t* b) {
    asm volatile(
        "mma.sync.aligned.m16n8k16.row.col.f32.f16.f16.f32 "
        "{%0,%1,%2,%3}, {%4,%5,%6,%7}, {%8,%9}, {%0,%1,%2,%3};\n"
        : "+f"(d[0]), "+f"(d[1]), "+f"(d[2]), "+f"(d[3])
        : "r"(a[0]), "r"(a[1]), "r"(a[2]), "r"(a[3]), "r"(b[0]), "r"(b[1]));
}

__device__ __forceinline__ void ldsm_x4(uint32_t* r, uint32_t a) {
    asm volatile("ldmatrix.sync.aligned.m8n8.x4.shared.b16 {%0,%1,%2,%3}, [%4];"
        : "=r"(r[0]), "=r"(r[1]), "=r"(r[2]), "=r"(r[3]) : "r"(a));
}
__device__ __forceinline__ void ldsm_x4_t(uint32_t* r, uint32_t a) {
    asm volatile("ldmatrix.sync.aligned.m8n8.x4.trans.shared.b16 {%0,%1,%2,%3}, [%4];"
        : "=r"(r[0]), "=r"(r[1]), "=r"(r[2]), "=r"(r[3]) : "r"(a));
}
__device__ __forceinline__ void cp_async16(uint32_t dst, const void* src) {
    asm volatile("cp.async.cg.shared.global [%0], [%1], 16;\n"
                 :: "r"(dst), "l"(src));
}
__device__ __forceinline__ void cp_commit() {
    asm volatile("cp.async.commit_group;\n");
}
__device__ __forceinline__ void cp_wait1() {
    asm volatile("cp.async.wait_group 1;\n");
}
__device__ __forceinline__ void cp_wait0() {
    asm volatile("cp.async.wait_group 0;\n");
}

// =====================================================================
// One-shot converter: 3 activations + 4 weights, fp32 -> fp16.
// grid (NBX, 7): y selects tensor; grid-stride over float4.
// =====================================================================
#define N4_ACT (M_*D_/4)   // 1048576
#define N4_W   (D_*D_/4)   // 262144

__global__ void cvt_all(const float* __restrict__ q, const float* __restrict__ k,
                        const float* __restrict__ v,
                        const float* __restrict__ wq, const float* __restrict__ wk,
                        const float* __restrict__ wv, const float* __restrict__ wo)
{
    const int seg = blockIdx.y;
    const float* src;
    __half* dst;
    int n4;
    switch (seg) {
        case 0: src = q;  dst = g_qin;           n4 = N4_ACT; break;
        case 1: src = k;  dst = g_kin;           n4 = N4_ACT; break;
        case 2: src = v;  dst = g_vin;           n4 = N4_ACT; break;
        case 3: src = wq; dst = g_w;             n4 = N4_W;   break;
        case 4: src = wk; dst = g_w + D_*D_;     n4 = N4_W;   break;
        case 5: src = wv; dst = g_w + 2*D_*D_;   n4 = N4_W;   break;
        default:src = wo; dst = g_w + 3*D_*D_;   n4 = N4_W;   break;
    }
    const int stride = gridDim.x * blockDim.x;
    for (int i = blockIdx.x * blockDim.x + threadIdx.x; i < n4; i += stride) {
        float4 x = ((const float4*)src)[i];
        ((uint2*)dst)[i] = make_uint2(h2_to_u32(__floats2half2_rn(x.x, x.y)),
                                      h2_to_u32(__floats2half2_rn(x.z, x.w)));
    }
}

// =====================================================================
// Pure-fp16 GEMM, 2-stage cp.async pipeline. CTA 128x128, BK=32,
// 256 threads / 8 warps (2m x 4n), warp 64x32. Direct register epilogue.
// =====================================================================
#define BKW 32
#define GLDT 40                       // smem LD (halves); 80B rows
#define STG (2*128*GLDT*2)            // per-stage bytes (A + W) = 20480
#define AOFS 0
#define WOFS (128*GLDT*2)             // 10240

struct GemmCtx {
    uint32_t sb;          // smem base
    uint32_t offA, offW;  // per-lane ldmatrix offsets (bytes)
    int crow, cch;        // cp.async chunk mapping
    int warp_m, warp_n;
    int lane;
};

__device__ __forceinline__ void gemm_init(GemmCtx& cx, void* smem) {
    const int tid = threadIdx.x;
    const int wid = tid >> 5;
    cx.lane = tid & 31;
    cx.warp_m = wid & 1;
    cx.warp_n = wid >> 1;
    cx.crow = tid >> 2;
    cx.cch  = tid & 3;
    cx.sb = (uint32_t)__cvta_generic_to_shared(smem);
    const int li = cx.lane >> 3, l7 = cx.lane & 7;
    cx.offA = ((uint32_t)((cx.warp_m*64 + ((li & 1) << 3) + l7) * GLDT
                           + ((li >> 1) << 3)) << 1);
    cx.offW = ((uint32_t)((cx.warp_n*32 + ((li >> 1) << 3) + l7) * GLDT
                           + ((li & 1) << 3)) << 1);
}

__device__ __forceinline__ void gemm_issue(const GemmCtx& cx,
    const __half* A, const __half* W, int m0, int n0, int kt, int s)
{
    const int k0 = kt * BKW;
    #pragma unroll
    for (int u = 0; u < 2; u++) {
        int row = cx.crow + u*64;
        cp_async16(cx.sb + s*STG + AOFS + ((row*GLDT + cx.cch*8) << 1),
                   &A[(size_t)(m0 + row)*1024 + k0 + cx.cch*8]);
        cp_async16(cx.sb + s*STG + WOFS + ((row*GLDT + cx.cch*8) << 1),
                   &W[(size_t)(n0 + row)*1024 + k0 + cx.cch*8]);
    }
    cp_commit();
}

__device__ __forceinline__ void gemm_mma(const GemmCtx& cx, float acc[4][4][4], int s)
{
    const uint32_t bA = cx.sb + s*STG + AOFS + cx.offA;
    const uint32_t bW = cx.sb + s*STG + WOFS + cx.offW;
    #pragma unroll
    for (int kk = 0; kk < BKW; kk += 16) {
        uint32_t ah[4][4];
        #pragma unroll
        for (int mt = 0; mt < 4; mt++)
            ldsm_x4(ah[mt], bA + ((mt*16*GLDT + kk) << 1));
        #pragma unroll
        for (int np = 0; np < 2; np++) {
            uint32_t wf[4];
            ldsm_x4(wf, bW + ((np*16*GLDT + kk) << 1));
            #pragma unroll
            for (int mt = 0; mt < 4; mt++) {
                mma16816(acc[mt][2*np],   ah[mt], wf);
                mma16816(acc[mt][2*np+1], ah[mt], wf + 2);
            }
        }
    }
}

// Fused QKV projections: grid.z selects {Q,K,V}; fp16 scatter epilogue.
__global__ void __launch_bounds__(256) gemm_qkv(
    const float* __restrict__ bq, const float* __restrict__ bk,
    const float* __restrict__ bv)
{
    __shared__ __half sbuf[2][STG/2];
    GemmCtx cx; gemm_init(cx, sbuf);

    const int z = blockIdx.z;
    const __half* A = (z == 0) ? g_qin : (z == 1) ? g_kin : g_vin;
    const __half* W = g_w + (size_t)z * D_*D_;
    const float* bias = (z == 0) ? bq : (z == 1) ? bk : bv;
    __half* outh = (z == 0) ? g_qh : (z == 1) ? g_kh : g_vh;
    const float sc = (z == 0) ? 0.125f : 1.0f;

    const int m0 = blockIdx.y * 128, n0 = blockIdx.x * 128;

    float acc[4][4][4];
    #pragma unroll
    for (int mt = 0; mt < 4; mt++)
        #pragma unroll
        for (int nt = 0; nt < 4; nt++)
            #pragma unroll
            for (int t = 0; t < 4; t++) acc[mt][nt][t] = 0.f;

    gemm_issue(cx, A, W, m0, n0, 0, 0);
    for (int kt = 0; kt < 1024/BKW; kt++) {
        if (kt + 1 < 1024/BKW) {
            gemm_issue(cx, A, W, m0, n0, kt + 1, (kt + 1) & 1);
            cp_wait1();
        } else {
            cp_wait0();
        }
        __syncthreads();
        gemm_mma(cx, acc, kt & 1);
        __syncthreads();
    }

    // direct register epilogue: fp16 scatter to [B,H,S,DH]
    const int g = cx.lane >> 2, c = cx.lane & 3;
    const int nw0 = n0 + cx.warp_n*32;
    const int hh = nw0 >> 6, d0 = nw0 & 63;
    #pragma unroll
    for (int mt = 0; mt < 4; mt++) {
        int gm0 = m0 + cx.warp_m*64 + mt*16 + g;
        int gm1 = gm0 + 8;
        int b0 = gm0 >> 11, s0 = gm0 & 2047;
        int b1 = gm1 >> 11, s1 = gm1 & 2047;
        #pragma unroll
        for (int nt = 0; nt < 4; nt++) {
            int col = nw0 + nt*8 + 2*c;
            float bx = bias[col], by = bias[col+1];
            float v0 = (acc[mt][nt][0] + bx) * sc;
            float v1 = (acc[mt][nt][1] + by) * sc;
            float v2 = (acc[mt][nt][2] + bx) * sc;
            float v3 = (acc[mt][nt][3] + by) * sc;
            int d = d0 + nt*8 + 2*c;
            size_t a0 = (((size_t)(b0*H_ + hh))*S_ + s0)*DH_ + d;
            size_t a1 = (((size_t)(b1*H_ + hh))*S_ + s1)*DH_ + d;
            *(uint32_t*)&outh[a0] = h2_to_u32(__floats2half2_rn(v0, v1));
            *(uint32_t*)&outh[a1] = h2_to_u32(__floats2half2_rn(v2, v3));
        }
    }
}

// O-projection: fp16 in (g_atth, g_w+3*D*D), fp32 out.
__global__ void __launch_bounds__(256) gemm_o(
    const float* __restrict__ bias, float* __restrict__ outf)
{
    __shared__ __half sbuf[2][STG/2];
    GemmCtx cx; gemm_init(cx, sbuf);

    const __half* A = g_atth;
    const __half* W = g_w + (size_t)3 * D_*D_;
    const int m0 = blockIdx.y * 128, n0 = blockIdx.x * 128;

    float acc[4][4][4];
    #pragma unroll
    for (int mt = 0; mt < 4; mt++)
        #pragma unroll
        for (int nt = 0; nt < 4; nt++)
            #pragma unroll
            for (int t = 0; t < 4; t++) acc[mt][nt][t] = 0.f;

    gemm_issue(cx, A, W, m0, n0, 0, 0);
    for (int kt = 0; kt < 1024/BKW; kt++) {
        if (kt + 1 < 1024/BKW) {
            gemm_issue(cx, A, W, m0, n0, kt + 1, (kt + 1) & 1);
            cp_wait1();
        } else {
            cp_wait0();
        }
        __syncthreads();
        gemm_mma(cx, acc, kt & 1);
        __syncthreads();
    }

    const int g = cx.lane >> 2, c = cx.lane & 3;
    const int nw0 = n0 + cx.warp_n*32;
    #pragma unroll
    for (int mt = 0; mt < 4; mt++) {
        int gm0 = m0 + cx.warp_m*64 + mt*16 + g;
        int gm1 = gm0 + 8;
        #pragma unroll
        for (int nt = 0; nt < 4; nt++) {
            int col = nw0 + nt*8 + 2*c;
            float bx = bias[col], by = bias[col+1];
            *(float2*)&outf[(size_t)gm0*1024 + col] =
                make_float2(acc[mt][nt][0] + bx, acc[mt][nt][1] + by);
            *(float2*)&outf[(size_t)gm1*1024 + col] =
                make_float2(acc[mt][nt][2] + bx, acc[mt][nt][3] + by);
        }
    }
}

// =====================================================================
// Flash attention — unchanged mainloop from R15/R16 (validated ~158us).
// Epilogue writes fp16 (same rounding previously applied inside gemm_o).
// =====================================================================
#define TLD 72          // leading dim (halves); 144B rows

#define AT_Q 0
#define AT_K (AT_Q + 128*TLD*2)          // 18432
#define AT_V (AT_K + 128*TLD*2)          // 36864
#define ATT_SMEM (AT_V + 128*TLD*2)      // 55296

__global__ void __launch_bounds__(256, 1) attn_mma()
{
    extern __shared__ char smem[];
    __half* Qs = (__half*)(smem + AT_Q);
    __half* Ks = (__half*)(smem + AT_K);
    __half* Vs = (__half*)(smem + AT_V);

    const int tid = threadIdx.x;
    const int wid = tid >> 5;
    const int lane = tid & 31;
    const int m0 = wid * 16;
    const int bh = blockIdx.y;
    const int q0 = blockIdx.x * 128;

    const __half* qbase = g_qh + (size_t)bh*S_*DH_;
    const __half* kbase = g_kh + (size_t)bh*S_*DH_;
    const __half* vbase = g_vh + (size_t)bh*S_*DH_;

    const int lrow = tid >> 3;
    const int lcu  = tid & 7;

    const uint32_t sb = (uint32_t)__cvta_generic_to_shared(smem);
    const int li = lane >> 3;
    const int l7 = lane & 7;
    const uint32_t aQ = sb + AT_Q +
        ((uint32_t)((m0 + ((li & 1) << 3) + l7) * TLD + ((li >> 1) << 3)) << 1);
    const uint32_t aK = sb + AT_K +
        ((uint32_t)((((li >> 1) << 3) + l7) * TLD + ((li & 1) << 3)) << 1);
    const uint32_t aV = sb + AT_V +
        ((uint32_t)((((li & 1) << 3) + l7) * TLD + ((li >> 1) << 3)) << 1);

    #pragma unroll
    for (int u = 0; u < 4; u++) {
        int row = lrow + u*32;
        uint4 vq = *(const uint4*)&qbase[(size_t)(q0 + row)*DH_ + lcu*8];
        *(uint4*)&Qs[row*TLD + lcu*8] = vq;
    }

    float O[8][4];
    #pragma unroll
    for (int n = 0; n < 8; n++)
        #pragma unroll
        for (int t = 0; t < 4; t++) O[n][t] = 0.f;
    float mr0 = -INFINITY, mr1 = -INFINITY;
    float lr0 = 0.f, lr1 = 0.f;

    for (int kt = 0; kt < S_/128; kt++) {
        const int k0g = kt * 128;
        uint4 rk[4], rv[4];
        #pragma unroll
        for (int u = 0; u < 4; u++) {
            int row = lrow + u*32;
            rk[u] = *(const uint4*)&kbase[(size_t)(k0g + row)*DH_ + lcu*8];
            rv[u] = *(const uint4*)&vbase[(size_t)(k0g + row)*DH_ + lcu*8];
        }
        __syncthreads();
        #pragma unroll
        for (int u = 0; u < 4; u++) {
            int row = lrow + u*32;
            *(uint4*)&Ks[row*TLD + lcu*8] = rk[u];
            *(uint4*)&Vs[row*TLD + lcu*8] = rv[u];
        }
        __syncthreads();

        float sacc[16][4];
        #pragma unroll
        for (int n = 0; n < 16; n++)
            #pragma unroll
            for (int t = 0; t < 4; t++) sacc[n][t] = 0.f;

        #pragma unroll
        for (int kk = 0; kk < 64; kk += 16) {
            uint32_t qf[4];
            ldsm_x4(qf, aQ + (kk << 1));
            #pragma unroll
            for (int np = 0; np < 8; np++) {
                uint32_t kf[4];
                ldsm_x4(kf, aK + ((np*16*TLD + kk) << 1));
                mma16816(sacc[2*np],   qf, kf);
                mma16816(sacc[2*np+1], qf, kf + 2);
            }
        }

        float mx0 = -INFINITY, mx1 = -INFINITY;
        #pragma unroll
        for (int n = 0; n < 16; n++) {
            mx0 = fmaxf(mx0, fmaxf(sacc[n][0], sacc[n][1]));
            mx1 = fmaxf(mx1, fmaxf(sacc[n][2], sacc[n][3]));
        }
        mx0 = fmaxf(mx0, __shfl_xor_sync(0xffffffffu, mx0, 1));
        mx0 = fmaxf(mx0, __shfl_xor_sync(0xffffffffu, mx0, 2));
        mx1 = fmaxf(mx1, __shfl_xor_sync(0xffffffffu, mx1, 1));
        mx1 = fmaxf(mx1, __shfl_xor_sync(0xffffffffu, mx1, 2));
        float m0n = fmaxf(mr0, mx0), m1n = fmaxf(mr1, mx1);
        float al0 = __expf(mr0 - m0n), al1 = __expf(mr1 - m1n);
        mr0 = m0n; mr1 = m1n;

        uint32_t pa[8][4];
        float sum0 = 0.f, sum1 = 0.f;
        #pragma unroll
        for (int j = 0; j < 8; j++) {
            float p00 = __expf(sacc[2*j][0] - m0n);
            float p01 = __expf(sacc[2*j][1] - m0n);
            float p10 = __expf(sacc[2*j][2] - m1n);
            float p11 = __expf(sacc[2*j][3] - m1n);
            float p04 = __expf(sacc[2*j+1][0] - m0n);
            float p05 = __expf(sacc[2*j+1][1] - m0n);
            float p14 = __expf(sacc[2*j+1][2] - m1n);
            float p15 = __expf(sacc[2*j+1][3] - m1n);
            sum0 += p00 + p01 + p04 + p05;
            sum1 += p10 + p11 + p14 + p15;
            pa[j][0] = h2_to_u32(__floats2half2_rn(p00, p01));
            pa[j][1] = h2_to_u32(__floats2half2_rn(p10, p11));
            pa[j][2] = h2_to_u32(__floats2half2_rn(p04, p05));
            pa[j][3] = h2_to_u32(__floats2half2_rn(p14, p15));
        }
        sum0 += __shfl_xor_sync(0xffffffffu, sum0, 1);
        sum0 += __shfl_xor_sync(0xffffffffu, sum0, 2);
        sum1 += __shfl_xor_sync(0xffffffffu, sum1, 1);
        sum1 += __shfl_xor_sync(0xffffffffu, sum1, 2);
        lr0 = lr0*al0 + sum0;
        lr1 = lr1*al1 + sum1;

        #pragma unroll
        for (int n = 0; n < 8; n++) {
            O[n][0] *= al0; O[n][1] *= al0;
            O[n][2] *= al1; O[n][3] *= al1;
        }
        #pragma unroll
        for (int j = 0; j < 8; j++) {
            #pragma unroll
            for (int nvp = 0; nvp < 4; nvp++) {
                uint32_t vf[4];
                ldsm_x4_t(vf, aV + ((j*16*TLD + nvp*16) << 1));
                mma16816(O[2*nvp],   pa[j], vf);
                mma16816(O[2*nvp+1], pa[j], vf + 2);
            }
        }
    }

    // ---- normalize + write fp16 [B,S,D] ----
    const int g = lane >> 2;
    const int c = lane & 3;
    const int b = bh >> 4, h = bh & 15;
    float il0 = 1.0f / lr0, il1 = 1.0f / lr1;
    const int r0 = q0 + m0 + g, r1 = r0 + 8;
    #pragma unroll
    for (int nv = 0; nv < 8; nv++) {
        int col = h*DH_ + nv*8 + 2*c;
        size_t a0 = ((size_t)(b*S_ + r0))*D_ + col;
        size_t a1 = ((size_t)(b*S_ + r1))*D_ + col;
        *(uint32_t*)&g_atth[a0] =
            h2_to_u32(__floats2half2_rn(O[nv][0]*il0, O[nv][1]*il0));
        *(uint32_t*)&g_atth[a1] =
            h2_to_u32(__floats2half2_rn(O[nv][2]*il1, O[nv][3]*il1));
    }
}

// =====================================================================
// Launch
// =====================================================================
extern "C" void kernel_launch(void* const* d_in, const int* in_sizes, int n_in,
                              void* d_out, int out_size)
{
    const float* query  = (const float*)d_in[0];
    const float* keys   = (const float*)d_in[1];
    const float* values = (const float*)d_in[2];
    const float* Wq = (const float*)d_in[3];
    const float* bq = (const float*)d_in[4];
    const float* Wk = (const float*)d_in[5];
    const float* bk = (const float*)d_in[6];
    const float* Wv = (const float*)d_in[7];
    const float* bv = (const float*)d_in[8];
    const float* Wo = (const float*)d_in[9];
    const float* bo = (const float*)d_in[10];
    float* out = (float*)d_out;

    cudaFuncSetAttribute(attn_mma,
                         cudaFuncAttributeMaxDynamicSharedMemorySize, ATT_SMEM);

    cvt_all<<<dim3(512, 7), 256>>>(query, keys, values, Wq, Wk, Wv, Wo);

    gemm_qkv<<<dim3(D_/128, M_/128, 3), 256>>>(bq, bk, bv);

    attn_mma<<<dim3(S_/128, B_*H_), 256, ATT_SMEM>>>();

    gemm_o<<<dim3(D_/128, M_/128), 256>>>(bo, out);
}